// round 3
// baseline (speedup 1.0000x reference)
#include <cuda_runtime.h>
#include <cuda_bf16.h>
#include <math.h>
#include <stdint.h>

// Problem shapes (fixed for this problem instance)
#define NB  256   // batch N
#define NT  512   // Nt
#define NX  512   // Nx

// ---------------------------------------------------------------------------
// Device scratch (no allocations allowed)
// ---------------------------------------------------------------------------
__device__ int    g_T0[NB];
__device__ double g_Wd[NX * NX];     // fp64 working copy of W for LU
__device__ double g_logabsdet;

// ---------------------------------------------------------------------------
// Kernel 1: per-sample T0 = min(argmin_t |phi[b,t,0]|, argmin_t |phi[b,t,1]|)
// argmin semantics: first occurrence of the minimum (strict < keeps first).
// One warp per sample.
// ---------------------------------------------------------------------------
__global__ void argmin_kernel(const float* __restrict__ phi) {
    int b = blockIdx.x;
    int lane = threadIdx.x;
    const float* p = phi + (size_t)b * NT * NX;

    float bv0 = 1e38f; int bi0 = 0;
    float bv1 = 1e38f; int bi1 = 0;
    for (int t = lane; t < NT; t += 32) {
        float v0 = fabsf(p[(size_t)t * NX + 0]);
        float v1 = fabsf(p[(size_t)t * NX + 1]);
        if (v0 < bv0) { bv0 = v0; bi0 = t; }
        if (v1 < bv1) { bv1 = v1; bi1 = t; }
    }
    #pragma unroll
    for (int o = 16; o; o >>= 1) {
        float ov = __shfl_down_sync(0xffffffffu, bv0, o);
        int   oi = __shfl_down_sync(0xffffffffu, bi0, o);
        if (ov < bv0 || (ov == bv0 && oi < bi0)) { bv0 = ov; bi0 = oi; }
        ov = __shfl_down_sync(0xffffffffu, bv1, o);
        oi = __shfl_down_sync(0xffffffffu, bi1, o);
        if (ov < bv1 || (ov == bv1 && oi < bi1)) { bv1 = ov; bi1 = oi; }
    }
    if (lane == 0) {
        g_T0[b] = (bi0 > bi1) ? bi1 : bi0;
    }
}

// ---------------------------------------------------------------------------
// Kernel 2: W (fp32) -> g_Wd (fp64), reset logdet accumulator
// ---------------------------------------------------------------------------
__global__ void convert_W_kernel(const float* __restrict__ W) {
    int i = blockIdx.x * blockDim.x + threadIdx.x;
    if (i < NX * NX) g_Wd[i] = (double)W[i];
    if (i == 0) g_logabsdet = 0.0;
}

// ---------------------------------------------------------------------------
// LU (fp64, partial pivoting, blocked nb=32). Only |pivot| products needed.
// ---------------------------------------------------------------------------
#define LU_NB 32

// Panel factorization: single block, panel held in shared memory.
// Also applies row swaps to the trailing columns [k0+32, 512) (LASWP),
// and accumulates sum(log|pivot|).
__global__ void lu_panel_kernel(int k0) {
    extern __shared__ double P[];           // R rows x 33 (padded)
    __shared__ double s_redv[16];
    __shared__ int    s_redi[16];
    __shared__ int    s_pivrow;
    __shared__ double s_pivinv;
    __shared__ double s_logsum;
    __shared__ int    s_piv[LU_NB];

    const int R = NX - k0;                  // active rows
    const int tid = threadIdx.x;            // 512 threads

    // Load panel into smem
    for (int i = tid; i < R * LU_NB; i += 512) {
        int r = i >> 5, c = i & 31;
        P[r * 33 + c] = g_Wd[(size_t)(k0 + r) * NX + k0 + c];
    }
    if (tid == 0) s_logsum = 0.0;
    __syncthreads();

    for (int j = 0; j < LU_NB; j++) {
        // --- pivot search over local rows r in [j, R) ---
        double v = -1.0; int idx = j;
        int r = j + tid;
        if (r < R) { v = fabs(P[r * 33 + j]); idx = r; }
        #pragma unroll
        for (int o = 16; o; o >>= 1) {
            double ov = __shfl_down_sync(0xffffffffu, v, o);
            int    oi = __shfl_down_sync(0xffffffffu, idx, o);
            if (ov > v) { v = ov; idx = oi; }
        }
        if ((tid & 31) == 0) { s_redv[tid >> 5] = v; s_redi[tid >> 5] = idx; }
        __syncthreads();
        if (tid == 0) {
            double bv = s_redv[0]; int bi = s_redi[0];
            for (int q = 1; q < 16; q++)
                if (s_redv[q] > bv) { bv = s_redv[q]; bi = s_redi[q]; }
            s_pivrow = bi; s_piv[j] = bi;
        }
        __syncthreads();
        int pr = s_pivrow;
        if (pr != j) {
            if (tid < LU_NB) {
                double t1 = P[j * 33 + tid];
                P[j * 33 + tid] = P[pr * 33 + tid];
                P[pr * 33 + tid] = t1;
            }
            __syncthreads();
        }
        if (tid == 0) {
            double pv = P[j * 33 + j];
            s_logsum += log(fabs(pv));
            s_pivinv = 1.0 / pv;
        }
        __syncthreads();
        double pinv = s_pivinv;
        // --- scale + rank-1 update of remaining panel columns ---
        r = j + 1 + tid;
        if (r < R) {
            double m = P[r * 33 + j] * pinv;
            P[r * 33 + j] = m;
            for (int c = j + 1; c < LU_NB; c++)
                P[r * 33 + c] -= m * P[j * 33 + c];
        }
        __syncthreads();
    }

    // Write back panel
    for (int i = tid; i < R * LU_NB; i += 512) {
        int r = i >> 5, c = i & 31;
        g_Wd[(size_t)(k0 + r) * NX + k0 + c] = P[r * 33 + c];
    }
    __syncthreads();

    // Apply recorded row swaps to trailing columns (columns < k0 never read again)
    int trail = NX - k0 - LU_NB;
    for (int j = 0; j < LU_NB; j++) {
        int pr = s_piv[j];
        if (pr != j) {
            for (int c = tid; c < trail; c += 512) {
                size_t a1 = (size_t)(k0 + j)  * NX + k0 + LU_NB + c;
                size_t a2 = (size_t)(k0 + pr) * NX + k0 + LU_NB + c;
                double t1 = g_Wd[a1]; g_Wd[a1] = g_Wd[a2]; g_Wd[a2] = t1;
            }
            __syncthreads();
        }
    }
    if (tid == 0) g_logabsdet += s_logsum;   // panel kernels serialize on stream
}

// U12 = L11^{-1} * A12 : one thread per trailing column, column in registers.
__global__ void lu_rowsolve_kernel(int k0) {
    __shared__ double L[LU_NB][LU_NB + 1];
    int cols2 = NX - k0 - LU_NB;
    for (int i = threadIdx.x; i < LU_NB * LU_NB; i += blockDim.x) {
        int r = i / LU_NB, c = i % LU_NB;
        L[r][c] = g_Wd[(size_t)(k0 + r) * NX + k0 + c];
    }
    __syncthreads();
    int c = blockIdx.x * blockDim.x + threadIdx.x;
    if (c >= cols2) return;
    int gc = k0 + LU_NB + c;
    double a[LU_NB];
    #pragma unroll
    for (int i = 0; i < LU_NB; i++) a[i] = g_Wd[(size_t)(k0 + i) * NX + gc];
    #pragma unroll
    for (int i = 0; i < LU_NB; i++) {
        #pragma unroll
        for (int r = i + 1; r < LU_NB; r++) a[r] -= L[r][i] * a[i];
    }
    #pragma unroll
    for (int i = 0; i < LU_NB; i++) g_Wd[(size_t)(k0 + i) * NX + gc] = a[i];
}

// A22 -= L21 * U12 (fp64, 32x32 tiles, inner dim 32). rows2/cols2 are
// multiples of 32, so no bounds checks needed.
__global__ void lu_trailing_kernel(int k0) {
    __shared__ double Ls[32][33];
    __shared__ double Us[32][33];
    int r0 = blockIdx.y * 32, c0 = blockIdx.x * 32;
    int tid = threadIdx.x;   // 256
    for (int i = tid; i < 32 * 32; i += 256) {
        int rr = i >> 5, cc = i & 31;
        Ls[rr][cc] = g_Wd[(size_t)(k0 + 32 + r0 + rr) * NX + k0 + cc];
        Us[rr][cc] = g_Wd[(size_t)(k0 + rr) * NX + k0 + 32 + c0 + cc];
    }
    __syncthreads();
    int tr = (tid >> 4) * 2;
    int tc = (tid & 15) * 2;
    double a00 = 0, a01 = 0, a10 = 0, a11 = 0;
    #pragma unroll
    for (int k = 0; k < 32; k++) {
        double l0 = Ls[tr][k], l1 = Ls[tr + 1][k];
        double u0 = Us[k][tc], u1 = Us[k][tc + 1];
        a00 += l0 * u0; a01 += l0 * u1; a10 += l1 * u0; a11 += l1 * u1;
    }
    size_t base = (size_t)(k0 + 32 + r0 + tr) * NX + k0 + 32 + c0 + tc;
    g_Wd[base]          -= a00;
    g_Wd[base + 1]      -= a01;
    g_Wd[base + NX]     -= a10;
    g_Wd[base + NX + 1] -= a11;
}

// logDet[i] = Nt * logabsdet  for all samples
__global__ void write_logdet_kernel(float* __restrict__ out_ld) {
    out_ld[threadIdx.x] = (float)((double)NT * g_logabsdet);
}

// ---------------------------------------------------------------------------
// Kernel 3: fused roll + GEMM + roll.
//   out[b, (t-T0)%Nt, y] = sum_u phi[b,t,u] * W[(u+T0)%Nx, y]
// Classic 128x128x8 double-buffered SGEMM, 256 threads, 8x8 per thread.
// ---------------------------------------------------------------------------
#define BM 128
#define BN 128
#define BK 8

__global__ __launch_bounds__(256, 2)
void gemm_roll_kernel(const float* __restrict__ phi,
                      const float* __restrict__ W,
                      float* __restrict__ out) {
    __shared__ __align__(16) float As[2][BK][BM];
    __shared__ __align__(16) float Bs[2][BK][BN];

    const int b  = blockIdx.z;
    const int n0 = blockIdx.x * BN;
    const int m0 = blockIdx.y * BM;
    const int T0 = g_T0[b];

    const float* A = phi + (size_t)b * NT * NX;
    float*       C = out + (size_t)b * NT * NX;

    const int tid  = threadIdx.x;
    const int arow = tid >> 1;           // 0..127
    const int acol = (tid & 1) * 4;      // 0 or 4
    const int br   = tid >> 5;           // 0..7
    const int bc   = (tid & 31) * 4;     // 0..124

    const int mreg = (tid >> 4) * 8;     // row offset in tile
    const int nreg = (tid & 15) * 8;     // col offset in tile

    float acc[8][8];
    #pragma unroll
    for (int i = 0; i < 8; i++)
        #pragma unroll
        for (int j = 0; j < 8; j++) acc[i][j] = 0.0f;

    // prefetch k-tile 0
    {
        float4 av = *(const float4*)(A + (size_t)(m0 + arow) * NX + acol);
        int brr = (br + T0) & (NX - 1);
        float4 bv = *(const float4*)(W + (size_t)brr * NX + n0 + bc);
        As[0][acol + 0][arow] = av.x;
        As[0][acol + 1][arow] = av.y;
        As[0][acol + 2][arow] = av.z;
        As[0][acol + 3][arow] = av.w;
        *(float4*)&Bs[0][br][bc] = bv;
    }
    __syncthreads();

    int buf = 0;
    const int KT = NX / BK;              // 64
    for (int kt = 0; kt < KT; kt++) {
        float4 av2, bv2;
        if (kt < KT - 1) {
            int k0 = (kt + 1) * BK;
            av2 = *(const float4*)(A + (size_t)(m0 + arow) * NX + k0 + acol);
            int brr = (k0 + br + T0) & (NX - 1);
            bv2 = *(const float4*)(W + (size_t)brr * NX + n0 + bc);
        }
        #pragma unroll
        for (int kk = 0; kk < BK; kk++) {
            float4 a0 = *(float4*)&As[buf][kk][mreg];
            float4 a1 = *(float4*)&As[buf][kk][mreg + 4];
            float4 b0 = *(float4*)&Bs[buf][kk][nreg];
            float4 b1 = *(float4*)&Bs[buf][kk][nreg + 4];
            float ar[8] = {a0.x, a0.y, a0.z, a0.w, a1.x, a1.y, a1.z, a1.w};
            float bg[8] = {b0.x, b0.y, b0.z, b0.w, b1.x, b1.y, b1.z, b1.w};
            #pragma unroll
            for (int i = 0; i < 8; i++)
                #pragma unroll
                for (int j = 0; j < 8; j++)
                    acc[i][j] += ar[i] * bg[j];
        }
        if (kt < KT - 1) {
            int nb = buf ^ 1;
            As[nb][acol + 0][arow] = av2.x;
            As[nb][acol + 1][arow] = av2.y;
            As[nb][acol + 2][arow] = av2.z;
            As[nb][acol + 3][arow] = av2.w;
            *(float4*)&Bs[nb][br][bc] = bv2;
            __syncthreads();
            buf = nb;
        }
    }

    // epilogue: row t -> output row (t - T0) mod Nt
    #pragma unroll
    for (int i = 0; i < 8; i++) {
        int t = m0 + mreg + i;
        int orow = (t - T0 + NT) & (NT - 1);
        float* crow = C + (size_t)orow * NX + n0 + nreg;
        *(float4*)(crow)     = make_float4(acc[i][0], acc[i][1], acc[i][2], acc[i][3]);
        *(float4*)(crow + 4) = make_float4(acc[i][4], acc[i][5], acc[i][6], acc[i][7]);
    }
}

// ---------------------------------------------------------------------------
// Launch
// ---------------------------------------------------------------------------
extern "C" void kernel_launch(void* const* d_in, const int* in_sizes, int n_in,
                              void* d_out, int out_size) {
    const float* phi = (const float*)d_in[0];
    const float* W   = (const float*)d_in[1];
    float* out = (float*)d_out;

    // panel kernel needs up to 512*33*8 = 135168 B dynamic smem
    cudaFuncSetAttribute(lu_panel_kernel,
                         cudaFuncAttributeMaxDynamicSharedMemorySize,
                         NX * 33 * (int)sizeof(double));

    // 1) T0 per sample
    argmin_kernel<<<NB, 32>>>(phi);

    // 2) fp64 LU of W for logabsdet
    convert_W_kernel<<<(NX * NX + 255) / 256, 256>>>(W);
    for (int p = 0; p < NX / LU_NB; p++) {
        int k0 = p * LU_NB;
        int R  = NX - k0;
        lu_panel_kernel<<<1, 512, R * 33 * (int)sizeof(double)>>>(k0);
        int cols2 = NX - k0 - LU_NB;
        if (cols2 > 0) {
            lu_rowsolve_kernel<<<(cols2 + 127) / 128, 128>>>(k0);
            dim3 g(cols2 / 32, cols2 / 32);
            lu_trailing_kernel<<<g, 256>>>(k0);
        }
    }
    write_logdet_kernel<<<1, NB>>>(out + (out_size - NB));

    // 3) fused roll->GEMM->roll
    dim3 grid(NX / BN, NT / BM, NB);
    gemm_roll_kernel<<<grid, 256>>>(phi, W, out);
}

// round 6
// speedup vs baseline: 1.0681x; 1.0681x over previous
#include <cuda_runtime.h>
#include <cuda_bf16.h>
#include <math.h>
#include <stdint.h>

#define NB  256
#define NT  512
#define NX  512

// ---------------------------------------------------------------------------
// Device scratch (static; no allocations anywhere)
// ---------------------------------------------------------------------------
__device__ __nv_bfloat16 g_phi_hi[(size_t)NB * NT * NX];  // rolled phi, hi half
__device__ __nv_bfloat16 g_phi_lo[(size_t)NB * NT * NX];  // rolled phi, lo half
__device__ __nv_bfloat16 g_wt_hi[(size_t)NX * NX];        // W^T hi  [y][x]
__device__ __nv_bfloat16 g_wt_lo[(size_t)NX * NX];        // W^T lo  [y][x]
__device__ int    g_T0[NB];
__device__ double g_Wd[NX * NX];
__device__ double g_logabsdet;

// ---------------------------------------------------------------------------
// PTX helpers (sm_80-era, safe on compute_103)
// ---------------------------------------------------------------------------
__device__ __forceinline__ uint32_t smem_u32(const void* p) {
    uint32_t a;
    asm("{ .reg .u64 t; cvta.to.shared.u64 t, %1; cvt.u32.u64 %0, t; }" : "=r"(a) : "l"(p));
    return a;
}
__device__ __forceinline__ void cp_async16(uint32_t dst, const void* src) {
    asm volatile("cp.async.cg.shared.global [%0], [%1], 16;" :: "r"(dst), "l"(src) : "memory");
}
#define CP_COMMIT() asm volatile("cp.async.commit_group;" ::: "memory")

__device__ __forceinline__ void ldsm_x4(uint32_t* r, uint32_t addr) {
    asm volatile("ldmatrix.sync.aligned.m8n8.x4.shared.b16 {%0,%1,%2,%3}, [%4];"
        : "=r"(r[0]), "=r"(r[1]), "=r"(r[2]), "=r"(r[3]) : "r"(addr));
}
__device__ __forceinline__ void mma16816(float* c, const uint32_t* a, const uint32_t* b) {
    asm volatile("mma.sync.aligned.m16n8k16.row.col.f32.bf16.bf16.f32 "
        "{%0,%1,%2,%3}, {%4,%5,%6,%7}, {%8,%9}, {%0,%1,%2,%3};"
        : "+f"(c[0]), "+f"(c[1]), "+f"(c[2]), "+f"(c[3])
        : "r"(a[0]), "r"(a[1]), "r"(a[2]), "r"(a[3]), "r"(b[0]), "r"(b[1]));
}

// ---------------------------------------------------------------------------
// argmin -> T0 per sample
// ---------------------------------------------------------------------------
__global__ void argmin_kernel(const float* __restrict__ phi) {
    int b = blockIdx.x, lane = threadIdx.x;
    const float* p = phi + (size_t)b * NT * NX;
    float bv0 = 1e38f; int bi0 = 0;
    float bv1 = 1e38f; int bi1 = 0;
    for (int t = lane; t < NT; t += 32) {
        float v0 = fabsf(p[(size_t)t * NX + 0]);
        float v1 = fabsf(p[(size_t)t * NX + 1]);
        if (v0 < bv0) { bv0 = v0; bi0 = t; }
        if (v1 < bv1) { bv1 = v1; bi1 = t; }
    }
    #pragma unroll
    for (int o = 16; o; o >>= 1) {
        float ov = __shfl_down_sync(0xffffffffu, bv0, o);
        int   oi = __shfl_down_sync(0xffffffffu, bi0, o);
        if (ov < bv0 || (ov == bv0 && oi < bi0)) { bv0 = ov; bi0 = oi; }
        ov = __shfl_down_sync(0xffffffffu, bv1, o);
        oi = __shfl_down_sync(0xffffffffu, bi1, o);
        if (ov < bv1 || (ov == bv1 && oi < bi1)) { bv1 = ov; bi1 = oi; }
    }
    if (lane == 0) g_T0[b] = (bi0 > bi1) ? bi1 : bi0;
}

// ---------------------------------------------------------------------------
// W prep: fp64 copy + transpose-split to bf16 hi/lo
// ---------------------------------------------------------------------------
__global__ void prep_W_kernel(const float* __restrict__ W) {
    __shared__ float t[32][33];
    int tx = threadIdx.x, ty = threadIdx.y;
    int r = blockIdx.y * 32 + ty, c = blockIdx.x * 32 + tx;
    float f = W[(size_t)r * NX + c];
    t[ty][tx] = f;
    g_Wd[(size_t)r * NX + c] = (double)f;
    if (blockIdx.x == 0 && blockIdx.y == 0 && tx == 0 && ty == 0) g_logabsdet = 0.0;
    __syncthreads();
    int rr = blockIdx.x * 32 + ty, cc = blockIdx.y * 32 + tx;
    float v = t[tx][ty];
    __nv_bfloat16 hi = __float2bfloat16(v);
    __nv_bfloat16 lo = __float2bfloat16(v - __bfloat162float(hi));
    g_wt_hi[(size_t)rr * NX + cc] = hi;
    g_wt_lo[(size_t)rr * NX + cc] = lo;
}

// ---------------------------------------------------------------------------
// phi prep: roll along x by +T0 and split to bf16 hi/lo.
//   phi_r[b,t,u'] = phi[b,t,(u'-T0) mod 512]
// ---------------------------------------------------------------------------
__global__ void prep_phi_kernel(const float* __restrict__ phi) {
    int row = blockIdx.x;                 // b*512 + t
    int b = row >> 9;
    int T0 = g_T0[b];
    const float* src = phi + (size_t)row * NX;
    __nv_bfloat16* dh = g_phi_hi + (size_t)row * NX;
    __nv_bfloat16* dl = g_phi_lo + (size_t)row * NX;
    for (int u = threadIdx.x; u < NX; u += 128) {
        float f = src[(u - T0) & (NX - 1)];
        __nv_bfloat16 hi = __float2bfloat16(f);
        __nv_bfloat16 lo = __float2bfloat16(f - __bfloat162float(hi));
        dh[u] = hi; dl[u] = lo;
    }
}

// ---------------------------------------------------------------------------
// LU panel (nb=32) + merged trsm. 1 block, 512 threads.
// ---------------------------------------------------------------------------
#define LU_NB 32

__global__ void lu_panel_kernel(int k0) {
    extern __shared__ double P[];           // R x 33
    __shared__ double s_redv[16];
    __shared__ int    s_redi[16];
    __shared__ int    s_pivrow;
    __shared__ double s_pivinv;
    __shared__ double s_logsum;
    __shared__ int    s_piv[LU_NB];

    const int R = NX - k0;
    const int tid = threadIdx.x;

    for (int i = tid; i < R * LU_NB; i += 512) {
        int r = i >> 5, c = i & 31;
        P[r * 33 + c] = g_Wd[(size_t)(k0 + r) * NX + k0 + c];
    }
    if (tid == 0) s_logsum = 0.0;
    __syncthreads();

    for (int j = 0; j < LU_NB; j++) {
        double v = -1.0; int idx = j;
        int r = j + tid;
        if (r < R) { v = fabs(P[r * 33 + j]); idx = r; }
        #pragma unroll
        for (int o = 16; o; o >>= 1) {
            double ov = __shfl_down_sync(0xffffffffu, v, o);
            int    oi = __shfl_down_sync(0xffffffffu, idx, o);
            if (ov > v) { v = ov; idx = oi; }
        }
        if ((tid & 31) == 0) { s_redv[tid >> 5] = v; s_redi[tid >> 5] = idx; }
        __syncthreads();
        if (tid == 0) {
            double bv = s_redv[0]; int bi = s_redi[0];
            for (int q = 1; q < 16; q++)
                if (s_redv[q] > bv) { bv = s_redv[q]; bi = s_redi[q]; }
            s_pivrow = bi; s_piv[j] = bi;
        }
        __syncthreads();
        int pr = s_pivrow;
        if (pr != j) {
            if (tid < LU_NB) {
                double t1 = P[j * 33 + tid];
                P[j * 33 + tid] = P[pr * 33 + tid];
                P[pr * 33 + tid] = t1;
            }
            __syncthreads();
        }
        if (tid == 0) {
            double pv = P[j * 33 + j];
            s_logsum += log(fabs(pv));
            s_pivinv = 1.0 / pv;
        }
        __syncthreads();
        double pinv = s_pivinv;
        r = j + 1 + tid;
        if (r < R) {
            double m = P[r * 33 + j] * pinv;
            P[r * 33 + j] = m;
            for (int c = j + 1; c < LU_NB; c++)
                P[r * 33 + c] -= m * P[j * 33 + c];
        }
        __syncthreads();
    }

    for (int i = tid; i < R * LU_NB; i += 512) {
        int r = i >> 5, c = i & 31;
        g_Wd[(size_t)(k0 + r) * NX + k0 + c] = P[r * 33 + c];
    }
    __syncthreads();

    int trail = NX - k0 - LU_NB;
    for (int j = 0; j < LU_NB; j++) {
        int pr = s_piv[j];
        if (pr != j) {
            for (int c = tid; c < trail; c += 512) {
                size_t a1 = (size_t)(k0 + j)  * NX + k0 + LU_NB + c;
                size_t a2 = (size_t)(k0 + pr) * NX + k0 + LU_NB + c;
                double t1 = g_Wd[a1]; g_Wd[a1] = g_Wd[a2]; g_Wd[a2] = t1;
            }
            __syncthreads();
        }
    }
    if (tid == 0) g_logabsdet += s_logsum;

    // merged trsm: U12 = L11^{-1} A12, one thread per trailing column
    if (tid < trail) {
        int gc = k0 + LU_NB + tid;
        double a[LU_NB];
        #pragma unroll
        for (int i = 0; i < LU_NB; i++) a[i] = g_Wd[(size_t)(k0 + i) * NX + gc];
        #pragma unroll
        for (int i = 0; i < LU_NB; i++) {
            double ai = a[i];
            #pragma unroll
            for (int rr = i + 1; rr < LU_NB; rr++) a[rr] -= P[rr * 33 + i] * ai;
        }
        #pragma unroll
        for (int i = 0; i < LU_NB; i++) g_Wd[(size_t)(k0 + i) * NX + gc] = a[i];
    }
}

__global__ void lu_trailing_kernel(int k0) {
    __shared__ double Ls[32][33];
    __shared__ double Us[32][33];
    int r0 = blockIdx.y * 32, c0 = blockIdx.x * 32;
    int tid = threadIdx.x;
    for (int i = tid; i < 32 * 32; i += 256) {
        int rr = i >> 5, cc = i & 31;
        Ls[rr][cc] = g_Wd[(size_t)(k0 + 32 + r0 + rr) * NX + k0 + cc];
        Us[rr][cc] = g_Wd[(size_t)(k0 + rr) * NX + k0 + 32 + c0 + cc];
    }
    __syncthreads();
    int tr = (tid >> 4) * 2, tc = (tid & 15) * 2;
    double a00 = 0, a01 = 0, a10 = 0, a11 = 0;
    #pragma unroll
    for (int k = 0; k < 32; k++) {
        double l0 = Ls[tr][k], l1 = Ls[tr + 1][k];
        double u0 = Us[k][tc], u1 = Us[k][tc + 1];
        a00 += l0 * u0; a01 += l0 * u1; a10 += l1 * u0; a11 += l1 * u1;
    }
    size_t base = (size_t)(k0 + 32 + r0 + tr) * NX + k0 + 32 + c0 + tc;
    g_Wd[base]          -= a00;
    g_Wd[base + 1]      -= a01;
    g_Wd[base + NX]     -= a10;
    g_Wd[base + NX + 1] -= a11;
}

__global__ void write_logdet_kernel(float* __restrict__ out_ld) {
    out_ld[threadIdx.x] = (float)((double)NT * g_logabsdet);
}

// ---------------------------------------------------------------------------
// HMMA bf16 GEMM, K = 3*512 concatenated (hi*hi, hi*lo, lo*hi).
// Tile 128x128, 8 warps (2x4 of 64x32 warp tiles), BK = 32 bf16,
// cp.async double-buffered smem, padded 80B rows (conflict-free ldmatrix).
// B fragment loaded with NON-trans ldmatrix (smem is Wt[n][k], K-major:
// each 32-bit reg must hold two consecutive k at fixed n).
// Epilogue: row t -> out row (t - T0) mod 512.
// ---------------------------------------------------------------------------
#define BM 128
#define BN 128
#define SROW 80                 // bytes per smem row (32 bf16 + 8 pad)
#define STAGE_BYTES (128 * SROW)
#define NITER 48                // 3 passes * 16 k-chunks of 32

__global__ void __launch_bounds__(256, 2)
gemm_tc_kernel(float* __restrict__ out) {
    __shared__ __align__(16) char sA[2][STAGE_BYTES];
    __shared__ __align__(16) char sB[2][STAGE_BYTES];

    const int tid  = threadIdx.x;
    const int lane = tid & 31;
    const int wid  = tid >> 5;
    const int wr   = wid >> 2;          // 0..1  (m)
    const int wc   = wid & 3;           // 0..3  (n)

    const int b  = blockIdx.z;
    const int n0 = blockIdx.x * BN;
    const int m0 = blockIdx.y * BM;
    const int T0 = g_T0[b];

    const uint32_t sAu = smem_u32(sA);
    const uint32_t sBu = smem_u32(sB);

    // pass sources
    const char* aP[3];
    const char* bP[3];
    {
        const char* ph = (const char*)(g_phi_hi + (size_t)b * NT * NX);
        const char* pl = (const char*)(g_phi_lo + (size_t)b * NT * NX);
        aP[0] = ph; aP[1] = ph; aP[2] = pl;
        bP[0] = (const char*)g_wt_hi; bP[1] = (const char*)g_wt_lo; bP[2] = (const char*)g_wt_hi;
    }

    // loader: 128 rows x 64 bytes per operand per stage; 256 thr x 2 chunks each
    auto load_iter = [&](int it) {
        int p = it >> 4, c = it & 15, s = it & 1;
        size_t kofs = (size_t)c * 64;
        const char* asrc = aP[p];
        const char* bsrc = bP[p];
        #pragma unroll
        for (int rep = 0; rep < 2; rep++) {
            int idx = tid + rep * 256;          // 0..511
            int row = idx >> 2;
            int q   = idx & 3;
            uint32_t dofs = (uint32_t)(row * SROW + q * 16);
            cp_async16(sAu + s * STAGE_BYTES + dofs,
                       asrc + (size_t)(m0 + row) * 1024 + kofs + q * 16);
            cp_async16(sBu + s * STAGE_BYTES + dofs,
                       bsrc + (size_t)(n0 + row) * 1024 + kofs + q * 16);
        }
        CP_COMMIT();
    };

    float acc[4][4][4];
    #pragma unroll
    for (int i = 0; i < 4; i++)
        #pragma unroll
        for (int j = 0; j < 4; j++)
            #pragma unroll
            for (int q = 0; q < 4; q++) acc[i][j][q] = 0.0f;

    // ldmatrix lane address components
    const int lm  = lane & 15;            // A: row within 16
    const int lk8 = lane >> 4;            // A: which k-8 half
    const int bn  = (lane & 7) + ((lane >> 4) << 3);   // B: n within 16 (two 8-blocks)
    const int bk8 = (lane >> 3) & 1;                   // B: k-8 half

    const uint32_t aLaneOfs = (uint32_t)((wr * 64 + lm) * SROW + lk8 * 16);
    const uint32_t bLaneOfs = (uint32_t)((wc * 32 + bn) * SROW + bk8 * 16);

    load_iter(0);

    for (int it = 0; it < NITER; it++) {
        int s = it & 1;
        if (it + 1 < NITER) {
            load_iter(it + 1);
            asm volatile("cp.async.wait_group 1;" ::: "memory");
        } else {
            asm volatile("cp.async.wait_group 0;" ::: "memory");
        }
        __syncthreads();

        const uint32_t aStage = sAu + s * STAGE_BYTES + aLaneOfs;
        const uint32_t bStage = sBu + s * STAGE_BYTES + bLaneOfs;

        #pragma unroll
        for (int ks = 0; ks < 2; ks++) {        // two k16 steps in BK=32
            uint32_t af[4][4];
            #pragma unroll
            for (int i = 0; i < 4; i++)
                ldsm_x4(af[i], aStage + i * (16 * SROW) + ks * 32);
            uint32_t bf[2][4];
            #pragma unroll
            for (int jp = 0; jp < 2; jp++)
                ldsm_x4(bf[jp], bStage + jp * (16 * SROW) + ks * 32);
            #pragma unroll
            for (int i = 0; i < 4; i++)
                #pragma unroll
                for (int j = 0; j < 4; j++)
                    mma16816(acc[i][j], af[i], &bf[j >> 1][(j & 1) * 2]);
        }
        __syncthreads();
    }

    // epilogue with fused output roll
    float* C = out + (size_t)b * NT * NX;
    #pragma unroll
    for (int i = 0; i < 4; i++) {
        int m_lo = m0 + wr * 64 + i * 16 + (lane >> 2);
        int m_hi = m_lo + 8;
        int or_lo = (m_lo - T0 + NT) & (NT - 1);
        int or_hi = (m_hi - T0 + NT) & (NT - 1);
        #pragma unroll
        for (int j = 0; j < 4; j++) {
            int col = n0 + wc * 32 + j * 8 + (lane & 3) * 2;
            *(float2*)(C + (size_t)or_lo * NX + col) = make_float2(acc[i][j][0], acc[i][j][1]);
            *(float2*)(C + (size_t)or_hi * NX + col) = make_float2(acc[i][j][2], acc[i][j][3]);
        }
    }
}

// ---------------------------------------------------------------------------
// Launch
// ---------------------------------------------------------------------------
extern "C" void kernel_launch(void* const* d_in, const int* in_sizes, int n_in,
                              void* d_out, int out_size) {
    const float* phi = (const float*)d_in[0];
    const float* W   = (const float*)d_in[1];
    float* out = (float*)d_out;

    cudaFuncSetAttribute(lu_panel_kernel,
                         cudaFuncAttributeMaxDynamicSharedMemorySize,
                         NX * 33 * (int)sizeof(double));

    // 1) T0, then prep (rolled split phi, transposed split W + fp64 copy)
    argmin_kernel<<<NB, 32>>>(phi);
    {
        dim3 g(NX / 32, NX / 32), blk(32, 32);
        prep_W_kernel<<<g, blk>>>(W);
    }
    prep_phi_kernel<<<NB * NT, 128>>>(phi);

    // 2) fp64 LU for logabsdet
    for (int p = 0; p < NX / LU_NB; p++) {
        int k0 = p * LU_NB;
        int R  = NX - k0;
        lu_panel_kernel<<<1, 512, R * 33 * (int)sizeof(double)>>>(k0);
        int cols2 = NX - k0 - LU_NB;
        if (cols2 > 0) {
            dim3 g(cols2 / 32, cols2 / 32);
            lu_trailing_kernel<<<g, 256>>>(k0);
        }
    }
    write_logdet_kernel<<<1, NB>>>(out + (out_size - NB));

    // 3) HMMA GEMM with fused output roll
    dim3 grid(NX / BN, NT / BM, NB);
    gemm_tc_kernel<<<grid, 256>>>(out);
}

// round 7
// speedup vs baseline: 1.7909x; 1.6767x over previous
#include <cuda_runtime.h>
#include <cuda_bf16.h>
#include <math.h>
#include <stdint.h>

#define NB  256
#define NT  512
#define NX  512

// ---------------------------------------------------------------------------
// Device scratch (static; no allocations anywhere)
// ---------------------------------------------------------------------------
__device__ __nv_bfloat16 g_phi_hi[(size_t)NB * NT * NX];  // rolled phi, hi half
__device__ __nv_bfloat16 g_phi_lo[(size_t)NB * NT * NX];  // rolled phi, lo half
__device__ __nv_bfloat16 g_wt_hi[(size_t)NX * NX];        // W^T hi  [y][x]
__device__ __nv_bfloat16 g_wt_lo[(size_t)NX * NX];        // W^T lo  [y][x]
__device__ int    g_T0[NB];
__device__ double g_Wd[NX * NX];
__device__ double g_logabsdet;

// ---------------------------------------------------------------------------
// PTX helpers (sm_80-era, safe on compute_103)
// ---------------------------------------------------------------------------
__device__ __forceinline__ uint32_t smem_u32(const void* p) {
    uint32_t a;
    asm("{ .reg .u64 t; cvta.to.shared.u64 t, %1; cvt.u32.u64 %0, t; }" : "=r"(a) : "l"(p));
    return a;
}
__device__ __forceinline__ void cp_async16(uint32_t dst, const void* src) {
    asm volatile("cp.async.cg.shared.global [%0], [%1], 16;" :: "r"(dst), "l"(src) : "memory");
}
#define CP_COMMIT() asm volatile("cp.async.commit_group;" ::: "memory")

__device__ __forceinline__ void ldsm_x4(uint32_t* r, uint32_t addr) {
    asm volatile("ldmatrix.sync.aligned.m8n8.x4.shared.b16 {%0,%1,%2,%3}, [%4];"
        : "=r"(r[0]), "=r"(r[1]), "=r"(r[2]), "=r"(r[3]) : "r"(addr));
}
__device__ __forceinline__ void mma16816(float* c, const uint32_t* a, const uint32_t* b) {
    asm volatile("mma.sync.aligned.m16n8k16.row.col.f32.bf16.bf16.f32 "
        "{%0,%1,%2,%3}, {%4,%5,%6,%7}, {%8,%9}, {%0,%1,%2,%3};"
        : "+f"(c[0]), "+f"(c[1]), "+f"(c[2]), "+f"(c[3])
        : "r"(a[0]), "r"(a[1]), "r"(a[2]), "r"(a[3]), "r"(b[0]), "r"(b[1]));
}

// ---------------------------------------------------------------------------
// argmin -> T0 per sample
// ---------------------------------------------------------------------------
__global__ void argmin_kernel(const float* __restrict__ phi) {
    int b = blockIdx.x, lane = threadIdx.x;
    const float* p = phi + (size_t)b * NT * NX;
    float bv0 = 1e38f; int bi0 = 0;
    float bv1 = 1e38f; int bi1 = 0;
    for (int t = lane; t < NT; t += 32) {
        float v0 = fabsf(p[(size_t)t * NX + 0]);
        float v1 = fabsf(p[(size_t)t * NX + 1]);
        if (v0 < bv0) { bv0 = v0; bi0 = t; }
        if (v1 < bv1) { bv1 = v1; bi1 = t; }
    }
    #pragma unroll
    for (int o = 16; o; o >>= 1) {
        float ov = __shfl_down_sync(0xffffffffu, bv0, o);
        int   oi = __shfl_down_sync(0xffffffffu, bi0, o);
        if (ov < bv0 || (ov == bv0 && oi < bi0)) { bv0 = ov; bi0 = oi; }
        ov = __shfl_down_sync(0xffffffffu, bv1, o);
        oi = __shfl_down_sync(0xffffffffu, bi1, o);
        if (ov < bv1 || (ov == bv1 && oi < bi1)) { bv1 = ov; bi1 = oi; }
    }
    if (lane == 0) g_T0[b] = (bi0 > bi1) ? bi1 : bi0;
}

// ---------------------------------------------------------------------------
// W prep: fp64 copy + transpose-split to bf16 hi/lo
// ---------------------------------------------------------------------------
__global__ void prep_W_kernel(const float* __restrict__ W) {
    __shared__ float t[32][33];
    int tx = threadIdx.x, ty = threadIdx.y;
    int r = blockIdx.y * 32 + ty, c = blockIdx.x * 32 + tx;
    float f = W[(size_t)r * NX + c];
    t[ty][tx] = f;
    g_Wd[(size_t)r * NX + c] = (double)f;
    if (blockIdx.x == 0 && blockIdx.y == 0 && tx == 0 && ty == 0) g_logabsdet = 0.0;
    __syncthreads();
    int rr = blockIdx.x * 32 + ty, cc = blockIdx.y * 32 + tx;
    float v = t[tx][ty];
    __nv_bfloat16 hi = __float2bfloat16(v);
    __nv_bfloat16 lo = __float2bfloat16(v - __bfloat162float(hi));
    g_wt_hi[(size_t)rr * NX + cc] = hi;
    g_wt_lo[(size_t)rr * NX + cc] = lo;
}

// ---------------------------------------------------------------------------
// phi prep: roll along x by +T0 and split to bf16 hi/lo.
// ---------------------------------------------------------------------------
__global__ void prep_phi_kernel(const float* __restrict__ phi) {
    int row = blockIdx.x;                 // b*512 + t
    int b = row >> 9;
    int T0 = g_T0[b];
    const float* src = phi + (size_t)row * NX;
    __nv_bfloat16* dh = g_phi_hi + (size_t)row * NX;
    __nv_bfloat16* dl = g_phi_lo + (size_t)row * NX;
    for (int u = threadIdx.x; u < NX; u += 128) {
        float f = src[(u - T0) & (NX - 1)];
        __nv_bfloat16 hi = __float2bfloat16(f);
        __nv_bfloat16 lo = __float2bfloat16(f - __bfloat162float(hi));
        dh[u] = hi; dl[u] = lo;
    }
}

// ---------------------------------------------------------------------------
// GENP LU panel (nb=32), register-resident rows, merged trsm, parallel
// pivot logs. One block, 512 threads. det is pivot-invariant; fp64 headroom
// makes no-pivot safe (even growth 1e6 -> logdet err ~1e-8).
// ---------------------------------------------------------------------------
#define LU_NB 32

__global__ void __launch_bounds__(512) lu_panel_genp(int k0) {
    __shared__ double s_u[LU_NB];
    __shared__ double s_pinv;
    __shared__ double s_piv[LU_NB];
    __shared__ double s_L[LU_NB][LU_NB + 1];

    const int tid = threadIdx.x;
    const int R = NX - k0;

    double a[LU_NB];
    if (tid < R) {
        const double* src = &g_Wd[(size_t)(k0 + tid) * NX + k0];
        #pragma unroll
        for (int c = 0; c < LU_NB; c++) a[c] = src[c];
    }
    __syncthreads();

    #pragma unroll
    for (int j = 0; j < LU_NB; j++) {
        if (tid == j) {
            s_piv[j]  = a[j];
            s_pinv    = 1.0 / a[j];
            #pragma unroll
            for (int c = 0; c < LU_NB; c++)
                if (c > j) s_u[c] = a[c];
        }
        __syncthreads();
        if (tid > j && tid < R) {
            double m = a[j] * s_pinv;
            a[j] = m;
            #pragma unroll
            for (int c = 0; c < LU_NB; c++)
                if (c > j) a[c] -= m * s_u[c];
        }
        __syncthreads();
    }

    // L11 to smem for the trsm; write panel (L21 + L11\U11) back to gmem
    if (tid < LU_NB) {
        #pragma unroll
        for (int c = 0; c < LU_NB; c++) s_L[tid][c] = a[c];
    }
    if (tid < R) {
        double* dst = &g_Wd[(size_t)(k0 + tid) * NX + k0];
        #pragma unroll
        for (int c = 0; c < LU_NB; c++) dst[c] = a[c];
    }
    __syncthreads();

    // merged trsm: U12 = L11^{-1} A12, one thread per trailing column
    const int trail = NX - k0 - LU_NB;
    if (tid < trail) {
        int gc = k0 + LU_NB + tid;
        #pragma unroll
        for (int i = 0; i < LU_NB; i++) a[i] = g_Wd[(size_t)(k0 + i) * NX + gc];
        #pragma unroll
        for (int i = 0; i < LU_NB; i++) {
            double ai = a[i];
            #pragma unroll
            for (int r = i + 1; r < LU_NB; r++) a[r] -= s_L[r][i] * ai;
        }
        #pragma unroll
        for (int i = 0; i < LU_NB; i++) g_Wd[(size_t)(k0 + i) * NX + gc] = a[i];
    }

    // parallel pivot logs (warp 0); one atomic per panel, panels serialize
    if (tid < 32) {
        double lg = log(fabs(s_piv[tid]));
        #pragma unroll
        for (int o = 16; o; o >>= 1) lg += __shfl_down_sync(0xffffffffu, lg, o);
        if (tid == 0) atomicAdd(&g_logabsdet, lg);
    }
}

// A22 -= L21 * U12 (fp64, 32x32 tiles)
__global__ void lu_trailing_kernel(int k0) {
    __shared__ double Ls[32][33];
    __shared__ double Us[32][33];
    int r0 = blockIdx.y * 32, c0 = blockIdx.x * 32;
    int tid = threadIdx.x;
    for (int i = tid; i < 32 * 32; i += 256) {
        int rr = i >> 5, cc = i & 31;
        Ls[rr][cc] = g_Wd[(size_t)(k0 + 32 + r0 + rr) * NX + k0 + cc];
        Us[rr][cc] = g_Wd[(size_t)(k0 + rr) * NX + k0 + 32 + c0 + cc];
    }
    __syncthreads();
    int tr = (tid >> 4) * 2, tc = (tid & 15) * 2;
    double a00 = 0, a01 = 0, a10 = 0, a11 = 0;
    #pragma unroll
    for (int k = 0; k < 32; k++) {
        double l0 = Ls[tr][k], l1 = Ls[tr + 1][k];
        double u0 = Us[k][tc], u1 = Us[k][tc + 1];
        a00 += l0 * u0; a01 += l0 * u1; a10 += l1 * u0; a11 += l1 * u1;
    }
    size_t base = (size_t)(k0 + 32 + r0 + tr) * NX + k0 + 32 + c0 + tc;
    g_Wd[base]          -= a00;
    g_Wd[base + 1]      -= a01;
    g_Wd[base + NX]     -= a10;
    g_Wd[base + NX + 1] -= a11;
}

__global__ void write_logdet_kernel(float* __restrict__ out_ld) {
    out_ld[threadIdx.x] = (float)((double)NT * g_logabsdet);
}

// ---------------------------------------------------------------------------
// HMMA bf16 GEMM, K = 3*512 concatenated (hi*hi, hi*lo, lo*hi).
// Tile 128x128, 8 warps, BK=32, cp.async double-buffered, fused output roll.
// ---------------------------------------------------------------------------
#define BM 128
#define BN 128
#define SROW 80                 // bytes per smem row (32 bf16 + 8 pad)
#define STAGE_BYTES (128 * SROW)
#define NITER 48                // 3 passes * 16 k-chunks of 32

__global__ void __launch_bounds__(256, 2)
gemm_tc_kernel(float* __restrict__ out) {
    __shared__ __align__(16) char sA[2][STAGE_BYTES];
    __shared__ __align__(16) char sB[2][STAGE_BYTES];

    const int tid  = threadIdx.x;
    const int lane = tid & 31;
    const int wid  = tid >> 5;
    const int wr   = wid >> 2;          // 0..1  (m)
    const int wc   = wid & 3;           // 0..3  (n)

    const int b  = blockIdx.z;
    const int n0 = blockIdx.x * BN;
    const int m0 = blockIdx.y * BM;
    const int T0 = g_T0[b];

    const uint32_t sAu = smem_u32(sA);
    const uint32_t sBu = smem_u32(sB);

    const char* aP[3];
    const char* bP[3];
    {
        const char* ph = (const char*)(g_phi_hi + (size_t)b * NT * NX);
        const char* pl = (const char*)(g_phi_lo + (size_t)b * NT * NX);
        aP[0] = ph; aP[1] = ph; aP[2] = pl;
        bP[0] = (const char*)g_wt_hi; bP[1] = (const char*)g_wt_lo; bP[2] = (const char*)g_wt_hi;
    }

    auto load_iter = [&](int it) {
        int p = it >> 4, c = it & 15, s = it & 1;
        size_t kofs = (size_t)c * 64;
        const char* asrc = aP[p];
        const char* bsrc = bP[p];
        #pragma unroll
        for (int rep = 0; rep < 2; rep++) {
            int idx = tid + rep * 256;          // 0..511
            int row = idx >> 2;
            int q   = idx & 3;
            uint32_t dofs = (uint32_t)(row * SROW + q * 16);
            cp_async16(sAu + s * STAGE_BYTES + dofs,
                       asrc + (size_t)(m0 + row) * 1024 + kofs + q * 16);
            cp_async16(sBu + s * STAGE_BYTES + dofs,
                       bsrc + (size_t)(n0 + row) * 1024 + kofs + q * 16);
        }
        CP_COMMIT();
    };

    float acc[4][4][4];
    #pragma unroll
    for (int i = 0; i < 4; i++)
        #pragma unroll
        for (int j = 0; j < 4; j++)
            #pragma unroll
            for (int q = 0; q < 4; q++) acc[i][j][q] = 0.0f;

    const int lm  = lane & 15;
    const int lk8 = lane >> 4;
    const int bn  = (lane & 7) + ((lane >> 4) << 3);
    const int bk8 = (lane >> 3) & 1;

    const uint32_t aLaneOfs = (uint32_t)((wr * 64 + lm) * SROW + lk8 * 16);
    const uint32_t bLaneOfs = (uint32_t)((wc * 32 + bn) * SROW + bk8 * 16);

    load_iter(0);

    for (int it = 0; it < NITER; it++) {
        int s = it & 1;
        if (it + 1 < NITER) {
            load_iter(it + 1);
            asm volatile("cp.async.wait_group 1;" ::: "memory");
        } else {
            asm volatile("cp.async.wait_group 0;" ::: "memory");
        }
        __syncthreads();

        const uint32_t aStage = sAu + s * STAGE_BYTES + aLaneOfs;
        const uint32_t bStage = sBu + s * STAGE_BYTES + bLaneOfs;

        #pragma unroll
        for (int ks = 0; ks < 2; ks++) {
            uint32_t af[4][4];
            #pragma unroll
            for (int i = 0; i < 4; i++)
                ldsm_x4(af[i], aStage + i * (16 * SROW) + ks * 32);
            uint32_t bf[2][4];
            #pragma unroll
            for (int jp = 0; jp < 2; jp++)
                ldsm_x4(bf[jp], bStage + jp * (16 * SROW) + ks * 32);
            #pragma unroll
            for (int i = 0; i < 4; i++)
                #pragma unroll
                for (int j = 0; j < 4; j++)
                    mma16816(acc[i][j], af[i], &bf[j >> 1][(j & 1) * 2]);
        }
        __syncthreads();
    }

    float* C = out + (size_t)b * NT * NX;
    #pragma unroll
    for (int i = 0; i < 4; i++) {
        int m_lo = m0 + wr * 64 + i * 16 + (lane >> 2);
        int m_hi = m_lo + 8;
        int or_lo = (m_lo - T0 + NT) & (NT - 1);
        int or_hi = (m_hi - T0 + NT) & (NT - 1);
        #pragma unroll
        for (int j = 0; j < 4; j++) {
            int col = n0 + wc * 32 + j * 8 + (lane & 3) * 2;
            *(float2*)(C + (size_t)or_lo * NX + col) = make_float2(acc[i][j][0], acc[i][j][1]);
            *(float2*)(C + (size_t)or_hi * NX + col) = make_float2(acc[i][j][2], acc[i][j][3]);
        }
    }
}

// ---------------------------------------------------------------------------
// Launch.  Order puts gemm_tc_kernel at launch index 5 so ncu (-s 5 -c 1)
// profiles it next round.
// ---------------------------------------------------------------------------
extern "C" void kernel_launch(void* const* d_in, const int* in_sizes, int n_in,
                              void* d_out, int out_size) {
    const float* phi = (const float*)d_in[0];
    const float* W   = (const float*)d_in[1];
    float* out = (float*)d_out;

    // 0,1,2: T0 + prep
    argmin_kernel<<<NB, 32>>>(phi);
    {
        dim3 g(NX / 32, NX / 32), blk(32, 32);
        prep_W_kernel<<<g, blk>>>(W);
    }
    prep_phi_kernel<<<NB * NT, 128>>>(phi);

    // 3,4: first LU round
    lu_panel_genp<<<1, 512>>>(0);
    {
        int cols2 = NX - LU_NB;
        dim3 g(cols2 / 32, cols2 / 32);
        lu_trailing_kernel<<<g, 256>>>(0);
    }

    // 5: the big GEMM (profiled)
    {
        dim3 grid(NX / BN, NT / BM, NB);
        gemm_tc_kernel<<<grid, 256>>>(out);
    }

    // remaining LU rounds
    for (int p = 1; p < NX / LU_NB; p++) {
        int k0 = p * LU_NB;
        lu_panel_genp<<<1, 512>>>(k0);
        int cols2 = NX - k0 - LU_NB;
        if (cols2 > 0) {
            dim3 g(cols2 / 32, cols2 / 32);
            lu_trailing_kernel<<<g, 256>>>(k0);
        }
    }
    write_logdet_kernel<<<1, NB>>>(out + (out_size - NB));
}

// round 8
// speedup vs baseline: 2.3973x; 1.3386x over previous
#include <cuda_runtime.h>
#include <cuda_bf16.h>
#include <math.h>
#include <stdint.h>

#define NB  256
#define NT  512
#define NX  512

// ---------------------------------------------------------------------------
// Device scratch (static; no allocations anywhere)
// ---------------------------------------------------------------------------
__device__ __nv_bfloat16 g_phi_hi[(size_t)NB * NT * NX];  // rolled phi, hi half
__device__ __nv_bfloat16 g_phi_lo[(size_t)NB * NT * NX];  // rolled phi, lo half
__device__ __nv_bfloat16 g_wt_hi[(size_t)NX * NX];        // W^T hi  [y][x]
__device__ __nv_bfloat16 g_wt_lo[(size_t)NX * NX];        // W^T lo  [y][x]
__device__ int    g_T0[NB];
__device__ double g_Wd[NX * NX];
__device__ double g_logabsdet;

// ---------------------------------------------------------------------------
// PTX helpers (sm_80-era, safe on compute_103)
// ---------------------------------------------------------------------------
__device__ __forceinline__ uint32_t smem_u32(const void* p) {
    uint32_t a;
    asm("{ .reg .u64 t; cvta.to.shared.u64 t, %1; cvt.u32.u64 %0, t; }" : "=r"(a) : "l"(p));
    return a;
}
__device__ __forceinline__ void cp_async16(uint32_t dst, const void* src) {
    asm volatile("cp.async.cg.shared.global [%0], [%1], 16;" :: "r"(dst), "l"(src) : "memory");
}
#define CP_COMMIT() asm volatile("cp.async.commit_group;" ::: "memory")

__device__ __forceinline__ void ldsm_x4(uint32_t* r, uint32_t addr) {
    asm volatile("ldmatrix.sync.aligned.m8n8.x4.shared.b16 {%0,%1,%2,%3}, [%4];"
        : "=r"(r[0]), "=r"(r[1]), "=r"(r[2]), "=r"(r[3]) : "r"(addr));
}
__device__ __forceinline__ void mma16816(float* c, const uint32_t* a, const uint32_t* b) {
    asm volatile("mma.sync.aligned.m16n8k16.row.col.f32.bf16.bf16.f32 "
        "{%0,%1,%2,%3}, {%4,%5,%6,%7}, {%8,%9}, {%0,%1,%2,%3};"
        : "+f"(c[0]), "+f"(c[1]), "+f"(c[2]), "+f"(c[3])
        : "r"(a[0]), "r"(a[1]), "r"(a[2]), "r"(a[3]), "r"(b[0]), "r"(b[1]));
}

// ---------------------------------------------------------------------------
// argmin -> T0 per sample
// ---------------------------------------------------------------------------
__global__ void argmin_kernel(const float* __restrict__ phi) {
    int b = blockIdx.x, lane = threadIdx.x;
    const float* p = phi + (size_t)b * NT * NX;
    float bv0 = 1e38f; int bi0 = 0;
    float bv1 = 1e38f; int bi1 = 0;
    for (int t = lane; t < NT; t += 32) {
        float v0 = fabsf(p[(size_t)t * NX + 0]);
        float v1 = fabsf(p[(size_t)t * NX + 1]);
        if (v0 < bv0) { bv0 = v0; bi0 = t; }
        if (v1 < bv1) { bv1 = v1; bi1 = t; }
    }
    #pragma unroll
    for (int o = 16; o; o >>= 1) {
        float ov = __shfl_down_sync(0xffffffffu, bv0, o);
        int   oi = __shfl_down_sync(0xffffffffu, bi0, o);
        if (ov < bv0 || (ov == bv0 && oi < bi0)) { bv0 = ov; bi0 = oi; }
        ov = __shfl_down_sync(0xffffffffu, bv1, o);
        oi = __shfl_down_sync(0xffffffffu, bi1, o);
        if (ov < bv1 || (ov == bv1 && oi < bi1)) { bv1 = ov; bi1 = oi; }
    }
    if (lane == 0) g_T0[b] = (bi0 > bi1) ? bi1 : bi0;
}

// ---------------------------------------------------------------------------
// W prep (main stream): transpose-split to bf16 hi/lo (GEMM B operand)
// ---------------------------------------------------------------------------
__global__ void prep_W_bf16(const float* __restrict__ W) {
    __shared__ float t[32][33];
    int tx = threadIdx.x, ty = threadIdx.y;
    int r = blockIdx.y * 32 + ty, c = blockIdx.x * 32 + tx;
    t[ty][tx] = W[(size_t)r * NX + c];
    __syncthreads();
    int rr = blockIdx.x * 32 + ty, cc = blockIdx.y * 32 + tx;
    float v = t[tx][ty];
    __nv_bfloat16 hi = __float2bfloat16(v);
    __nv_bfloat16 lo = __float2bfloat16(v - __bfloat162float(hi));
    g_wt_hi[(size_t)rr * NX + cc] = hi;
    g_wt_lo[(size_t)rr * NX + cc] = lo;
}

// ---------------------------------------------------------------------------
// W prep (side stream): fp64 copy + logdet reset
// ---------------------------------------------------------------------------
__global__ void convert_Wd(const float* __restrict__ W) {
    int i = blockIdx.x * blockDim.x + threadIdx.x;
    if (i < NX * NX) g_Wd[i] = (double)W[i];
    if (i == 0) g_logabsdet = 0.0;
}

// ---------------------------------------------------------------------------
// phi prep: roll along x by +T0 and split to bf16 hi/lo.
// ---------------------------------------------------------------------------
__global__ void prep_phi_kernel(const float* __restrict__ phi) {
    int row = blockIdx.x;                 // b*512 + t
    int b = row >> 9;
    int T0 = g_T0[b];
    const float* src = phi + (size_t)row * NX;
    __nv_bfloat16* dh = g_phi_hi + (size_t)row * NX;
    __nv_bfloat16* dl = g_phi_lo + (size_t)row * NX;
    for (int u = threadIdx.x; u < NX; u += 128) {
        float f = src[(u - T0) & (NX - 1)];
        __nv_bfloat16 hi = __float2bfloat16(f);
        __nv_bfloat16 lo = __float2bfloat16(f - __bfloat162float(hi));
        dh[u] = hi; dl[u] = lo;
    }
}

// ---------------------------------------------------------------------------
// GENP LU panel (nb=16), register-resident rows, merged trsm, parallel
// pivot logs. One block, 512 threads. Serial fp64 work scales with nb, so
// nb=16 halves the critical path vs nb=32.
// ---------------------------------------------------------------------------
#define LU_NB 16

__global__ void __launch_bounds__(512) lu_panel_genp(int k0) {
    __shared__ double s_u[LU_NB];
    __shared__ double s_pinv;
    __shared__ double s_piv[LU_NB];
    __shared__ double s_L[LU_NB][LU_NB + 1];

    const int tid = threadIdx.x;
    const int R = NX - k0;

    double a[LU_NB];
    if (tid < R) {
        const double* src = &g_Wd[(size_t)(k0 + tid) * NX + k0];
        #pragma unroll
        for (int c = 0; c < LU_NB; c++) a[c] = src[c];
    }
    __syncthreads();

    #pragma unroll
    for (int j = 0; j < LU_NB; j++) {
        if (tid == j) {
            s_piv[j]  = a[j];
            s_pinv    = 1.0 / a[j];
            #pragma unroll
            for (int c = 0; c < LU_NB; c++)
                if (c > j) s_u[c] = a[c];
        }
        __syncthreads();
        if (tid > j && tid < R) {
            double m = a[j] * s_pinv;
            a[j] = m;
            #pragma unroll
            for (int c = 0; c < LU_NB; c++)
                if (c > j) a[c] -= m * s_u[c];
        }
        __syncthreads();
    }

    if (tid < LU_NB) {
        #pragma unroll
        for (int c = 0; c < LU_NB; c++) s_L[tid][c] = a[c];
    }
    if (tid < R) {
        double* dst = &g_Wd[(size_t)(k0 + tid) * NX + k0];
        #pragma unroll
        for (int c = 0; c < LU_NB; c++) dst[c] = a[c];
    }
    __syncthreads();

    // merged trsm: U12 = L11^{-1} A12, one thread per trailing column
    const int trail = NX - k0 - LU_NB;     // max 496 <= 512 threads
    if (tid < trail) {
        int gc = k0 + LU_NB + tid;
        #pragma unroll
        for (int i = 0; i < LU_NB; i++) a[i] = g_Wd[(size_t)(k0 + i) * NX + gc];
        #pragma unroll
        for (int i = 0; i < LU_NB; i++) {
            double ai = a[i];
            #pragma unroll
            for (int r = i + 1; r < LU_NB; r++) a[r] -= s_L[r][i] * ai;
        }
        #pragma unroll
        for (int i = 0; i < LU_NB; i++) g_Wd[(size_t)(k0 + i) * NX + gc] = a[i];
    }

    // pivot logs (first 16 lanes of warp 0); one atomic per panel (serialized
    // by stream order -> deterministic)
    if (tid < 32) {
        double lg = (tid < LU_NB) ? log(fabs(s_piv[tid])) : 0.0;
        #pragma unroll
        for (int o = 16; o; o >>= 1) lg += __shfl_down_sync(0xffffffffu, lg, o);
        if (tid == 0) atomicAdd(&g_logabsdet, lg);
    }
}

// A22 -= L21 * U12, K=16, 16x16 output tile per block, 256 threads.
__global__ void lu_trailing16(int k0) {
    __shared__ double Ls[16][17];
    __shared__ double Us[16][17];
    int r0 = blockIdx.y * 16, c0 = blockIdx.x * 16;
    int tid = threadIdx.x;               // 256
    int rr = tid >> 4, cc = tid & 15;
    Ls[rr][cc] = g_Wd[(size_t)(k0 + 16 + r0 + rr) * NX + k0 + cc];
    Us[rr][cc] = g_Wd[(size_t)(k0 + rr) * NX + k0 + 16 + c0 + cc];
    __syncthreads();
    double s = 0.0;
    #pragma unroll
    for (int k = 0; k < 16; k++) s += Ls[rr][k] * Us[k][cc];
    g_Wd[(size_t)(k0 + 16 + r0 + rr) * NX + k0 + 16 + c0 + cc] -= s;
}

__global__ void write_logdet_kernel(float* __restrict__ out_ld) {
    out_ld[threadIdx.x] = (float)((double)NT * g_logabsdet);
}

// ---------------------------------------------------------------------------
// HMMA bf16 GEMM, K = 3*512 concatenated (hi*hi, hi*lo, lo*hi).
// Tile 128x128, 8 warps, BK=32, cp.async double-buffered, fused output roll.
// ---------------------------------------------------------------------------
#define BM 128
#define BN 128
#define SROW 80                 // bytes per smem row (32 bf16 + 8 pad)
#define STAGE_BYTES (128 * SROW)
#define NITER 48                // 3 passes * 16 k-chunks of 32

__global__ void __launch_bounds__(256, 2)
gemm_tc_kernel(float* __restrict__ out) {
    __shared__ __align__(16) char sA[2][STAGE_BYTES];
    __shared__ __align__(16) char sB[2][STAGE_BYTES];

    const int tid  = threadIdx.x;
    const int lane = tid & 31;
    const int wid  = tid >> 5;
    const int wr   = wid >> 2;          // 0..1  (m)
    const int wc   = wid & 3;           // 0..3  (n)

    const int b  = blockIdx.z;
    const int n0 = blockIdx.x * BN;
    const int m0 = blockIdx.y * BM;
    const int T0 = g_T0[b];

    const uint32_t sAu = smem_u32(sA);
    const uint32_t sBu = smem_u32(sB);

    const char* aP[3];
    const char* bP[3];
    {
        const char* ph = (const char*)(g_phi_hi + (size_t)b * NT * NX);
        const char* pl = (const char*)(g_phi_lo + (size_t)b * NT * NX);
        aP[0] = ph; aP[1] = ph; aP[2] = pl;
        bP[0] = (const char*)g_wt_hi; bP[1] = (const char*)g_wt_lo; bP[2] = (const char*)g_wt_hi;
    }

    auto load_iter = [&](int it) {
        int p = it >> 4, c = it & 15, s = it & 1;
        size_t kofs = (size_t)c * 64;
        const char* asrc = aP[p];
        const char* bsrc = bP[p];
        #pragma unroll
        for (int rep = 0; rep < 2; rep++) {
            int idx = tid + rep * 256;          // 0..511
            int row = idx >> 2;
            int q   = idx & 3;
            uint32_t dofs = (uint32_t)(row * SROW + q * 16);
            cp_async16(sAu + s * STAGE_BYTES + dofs,
                       asrc + (size_t)(m0 + row) * 1024 + kofs + q * 16);
            cp_async16(sBu + s * STAGE_BYTES + dofs,
                       bsrc + (size_t)(n0 + row) * 1024 + kofs + q * 16);
        }
        CP_COMMIT();
    };

    float acc[4][4][4];
    #pragma unroll
    for (int i = 0; i < 4; i++)
        #pragma unroll
        for (int j = 0; j < 4; j++)
            #pragma unroll
            for (int q = 0; q < 4; q++) acc[i][j][q] = 0.0f;

    const int lm  = lane & 15;
    const int lk8 = lane >> 4;
    const int bn  = (lane & 7) + ((lane >> 4) << 3);
    const int bk8 = (lane >> 3) & 1;

    const uint32_t aLaneOfs = (uint32_t)((wr * 64 + lm) * SROW + lk8 * 16);
    const uint32_t bLaneOfs = (uint32_t)((wc * 32 + bn) * SROW + bk8 * 16);

    load_iter(0);

    for (int it = 0; it < NITER; it++) {
        int s = it & 1;
        if (it + 1 < NITER) {
            load_iter(it + 1);
            asm volatile("cp.async.wait_group 1;" ::: "memory");
        } else {
            asm volatile("cp.async.wait_group 0;" ::: "memory");
        }
        __syncthreads();

        const uint32_t aStage = sAu + s * STAGE_BYTES + aLaneOfs;
        const uint32_t bStage = sBu + s * STAGE_BYTES + bLaneOfs;

        #pragma unroll
        for (int ks = 0; ks < 2; ks++) {
            uint32_t af[4][4];
            #pragma unroll
            for (int i = 0; i < 4; i++)
                ldsm_x4(af[i], aStage + i * (16 * SROW) + ks * 32);
            uint32_t bf[2][4];
            #pragma unroll
            for (int jp = 0; jp < 2; jp++)
                ldsm_x4(bf[jp], bStage + jp * (16 * SROW) + ks * 32);
            #pragma unroll
            for (int i = 0; i < 4; i++)
                #pragma unroll
                for (int j = 0; j < 4; j++)
                    mma16816(acc[i][j], af[i], &bf[j >> 1][(j & 1) * 2]);
        }
        __syncthreads();
    }

    float* C = out + (size_t)b * NT * NX;
    #pragma unroll
    for (int i = 0; i < 4; i++) {
        int m_lo = m0 + wr * 64 + i * 16 + (lane >> 2);
        int m_hi = m_lo + 8;
        int or_lo = (m_lo - T0 + NT) & (NT - 1);
        int or_hi = (m_hi - T0 + NT) & (NT - 1);
        #pragma unroll
        for (int j = 0; j < 4; j++) {
            int col = n0 + wc * 32 + j * 8 + (lane & 3) * 2;
            *(float2*)(C + (size_t)or_lo * NX + col) = make_float2(acc[i][j][0], acc[i][j][1]);
            *(float2*)(C + (size_t)or_hi * NX + col) = make_float2(acc[i][j][2], acc[i][j][3]);
        }
    }
}

// ---------------------------------------------------------------------------
// Launch. Main stream: argmin(0), prepW(1), prep_phi(2), GEMM(3 <- profiled).
// Side stream (forked via events, capture-legal): fp64 LU chain + logdet.
// Lazy stream/event creation happens on the first (non-captured) correctness
// call; the captured call only records/waits events = graph fork/join.
// ---------------------------------------------------------------------------
extern "C" void kernel_launch(void* const* d_in, const int* in_sizes, int n_in,
                              void* d_out, int out_size) {
    const float* phi = (const float*)d_in[0];
    const float* W   = (const float*)d_in[1];
    float* out = (float*)d_out;

    static cudaStream_t s_side = nullptr;
    static cudaEvent_t  s_fork = nullptr, s_join = nullptr;
    if (s_side == nullptr) {
        cudaStreamCreateWithFlags(&s_side, cudaStreamNonBlocking);
        cudaEventCreateWithFlags(&s_fork, cudaEventDisableTiming);
        cudaEventCreateWithFlags(&s_join, cudaEventDisableTiming);
    }

    // fork: side stream depends on stream-0 state at entry
    cudaEventRecord(s_fork, 0);
    cudaStreamWaitEvent(s_side, s_fork, 0);

    // ---- main stream ----
    argmin_kernel<<<NB, 32>>>(phi);                       // our launch 0
    {
        dim3 g(NX / 32, NX / 32), blk(32, 32);
        prep_W_bf16<<<g, blk>>>(W);                       // our launch 1
    }
    prep_phi_kernel<<<NB * NT, 128>>>(phi);               // our launch 2
    {
        dim3 grid(NX / BN, NT / BM, NB);
        gemm_tc_kernel<<<grid, 256>>>(out);               // our launch 3 (ncu target)
    }

    // ---- side stream: logdet chain (independent of main until join) ----
    convert_Wd<<<(NX * NX + 255) / 256, 256, 0, s_side>>>(W);
    for (int p = 0; p < NX / LU_NB; p++) {
        int k0 = p * LU_NB;
        lu_panel_genp<<<1, 512, 0, s_side>>>(k0);
        int cols2 = NX - k0 - LU_NB;
        if (cols2 > 0) {
            dim3 g(cols2 / 16, cols2 / 16);
            lu_trailing16<<<g, 256, 0, s_side>>>(k0);
        }
    }
    write_logdet_kernel<<<1, NB, 0, s_side>>>(out + (out_size - NB));

    // join: stream 0 (and thus the graph's end) depends on the side chain
    cudaEventRecord(s_join, s_side);
    cudaStreamWaitEvent(0, s_join, 0);
}

// round 9
// speedup vs baseline: 2.5443x; 1.0613x over previous
#include <cuda_runtime.h>
#include <cuda_bf16.h>
#include <math.h>
#include <stdint.h>

#define NB  256
#define NT  512
#define NX  512

// ---------------------------------------------------------------------------
// Device scratch (static; no allocations anywhere)
// ---------------------------------------------------------------------------
__device__ __nv_bfloat16 g_phi_hi[(size_t)NB * NT * NX];  // rolled phi, hi half
__device__ __nv_bfloat16 g_phi_lo[(size_t)NB * NT * NX];  // rolled phi, lo half
__device__ __nv_bfloat16 g_wt_hi[(size_t)NX * NX];        // W^T hi  [y][x]
__device__ __nv_bfloat16 g_wt_lo[(size_t)NX * NX];        // W^T lo  [y][x]
__device__ int    g_T0[NB];
__device__ double g_Wd[NX * NX];
__device__ double g_logabsdet;

// ---------------------------------------------------------------------------
// PTX helpers (sm_80-era, safe on compute_103)
// ---------------------------------------------------------------------------
__device__ __forceinline__ uint32_t smem_u32(const void* p) {
    uint32_t a;
    asm("{ .reg .u64 t; cvta.to.shared.u64 t, %1; cvt.u32.u64 %0, t; }" : "=r"(a) : "l"(p));
    return a;
}
__device__ __forceinline__ void cp_async16(uint32_t dst, const void* src) {
    asm volatile("cp.async.cg.shared.global [%0], [%1], 16;" :: "r"(dst), "l"(src) : "memory");
}
#define CP_COMMIT() asm volatile("cp.async.commit_group;" ::: "memory")

__device__ __forceinline__ void ldsm_x4(uint32_t* r, uint32_t addr) {
    asm volatile("ldmatrix.sync.aligned.m8n8.x4.shared.b16 {%0,%1,%2,%3}, [%4];"
        : "=r"(r[0]), "=r"(r[1]), "=r"(r[2]), "=r"(r[3]) : "r"(addr));
}
__device__ __forceinline__ void mma16816(float* c, const uint32_t* a, const uint32_t* b) {
    asm volatile("mma.sync.aligned.m16n8k16.row.col.f32.bf16.bf16.f32 "
        "{%0,%1,%2,%3}, {%4,%5,%6,%7}, {%8,%9}, {%0,%1,%2,%3};"
        : "+f"(c[0]), "+f"(c[1]), "+f"(c[2]), "+f"(c[3])
        : "r"(a[0]), "r"(a[1]), "r"(a[2]), "r"(a[3]), "r"(b[0]), "r"(b[1]));
}

// ---------------------------------------------------------------------------
// argmin -> T0 per sample
// ---------------------------------------------------------------------------
__global__ void argmin_kernel(const float* __restrict__ phi) {
    int b = blockIdx.x, lane = threadIdx.x;
    const float* p = phi + (size_t)b * NT * NX;
    float bv0 = 1e38f; int bi0 = 0;
    float bv1 = 1e38f; int bi1 = 0;
    for (int t = lane; t < NT; t += 32) {
        float v0 = fabsf(p[(size_t)t * NX + 0]);
        float v1 = fabsf(p[(size_t)t * NX + 1]);
        if (v0 < bv0) { bv0 = v0; bi0 = t; }
        if (v1 < bv1) { bv1 = v1; bi1 = t; }
    }
    #pragma unroll
    for (int o = 16; o; o >>= 1) {
        float ov = __shfl_down_sync(0xffffffffu, bv0, o);
        int   oi = __shfl_down_sync(0xffffffffu, bi0, o);
        if (ov < bv0 || (ov == bv0 && oi < bi0)) { bv0 = ov; bi0 = oi; }
        ov = __shfl_down_sync(0xffffffffu, bv1, o);
        oi = __shfl_down_sync(0xffffffffu, bi1, o);
        if (ov < bv1 || (ov == bv1 && oi < bi1)) { bv1 = ov; bi1 = oi; }
    }
    if (lane == 0) g_T0[b] = (bi0 > bi1) ? bi1 : bi0;
}

// ---------------------------------------------------------------------------
// W prep (main stream): transpose-split to bf16 hi/lo (GEMM B operand)
// ---------------------------------------------------------------------------
__global__ void prep_W_bf16(const float* __restrict__ W) {
    __shared__ float t[32][33];
    int tx = threadIdx.x, ty = threadIdx.y;
    int r = blockIdx.y * 32 + ty, c = blockIdx.x * 32 + tx;
    t[ty][tx] = W[(size_t)r * NX + c];
    __syncthreads();
    int rr = blockIdx.x * 32 + ty, cc = blockIdx.y * 32 + tx;
    float v = t[tx][ty];
    __nv_bfloat16 hi = __float2bfloat16(v);
    __nv_bfloat16 lo = __float2bfloat16(v - __bfloat162float(hi));
    g_wt_hi[(size_t)rr * NX + cc] = hi;
    g_wt_lo[(size_t)rr * NX + cc] = lo;
}

// ---------------------------------------------------------------------------
// W prep (side stream): fp64 copy + logdet reset
// ---------------------------------------------------------------------------
__global__ void convert_Wd(const float* __restrict__ W) {
    int i = blockIdx.x * blockDim.x + threadIdx.x;
    if (i < NX * NX) g_Wd[i] = (double)W[i];
    if (i == 0) g_logabsdet = 0.0;
}

// ---------------------------------------------------------------------------
// phi prep: roll along x by +T0 and split to bf16 hi/lo.
// ---------------------------------------------------------------------------
__global__ void prep_phi_kernel(const float* __restrict__ phi) {
    int row = blockIdx.x;                 // b*512 + t
    int b = row >> 9;
    int T0 = g_T0[b];
    const float* src = phi + (size_t)row * NX;
    __nv_bfloat16* dh = g_phi_hi + (size_t)row * NX;
    __nv_bfloat16* dl = g_phi_lo + (size_t)row * NX;
    for (int u = threadIdx.x; u < NX; u += 128) {
        float f = src[(u - T0) & (NX - 1)];
        __nv_bfloat16 hi = __float2bfloat16(f);
        __nv_bfloat16 lo = __float2bfloat16(f - __bfloat162float(hi));
        dh[u] = hi; dl[u] = lo;
    }
}

// ---------------------------------------------------------------------------
// GENP LU panel (nb=16): column loop ONLY (no trsm — trailing blocks
// recompute their U12 slice locally; U12 is never needed again).
// One block, 512 threads, register-resident rows. fp64 serial work here is
// the logdet critical path: ~R*128 DFMA per panel.
// ---------------------------------------------------------------------------
#define LU_NB 16

__global__ void __launch_bounds__(512) lu_panel_genp(int k0) {
    __shared__ double s_u[LU_NB];
    __shared__ double s_pinv;
    __shared__ double s_piv[LU_NB];

    const int tid = threadIdx.x;
    const int R = NX - k0;

    double a[LU_NB];
    if (tid < R) {
        const double* src = &g_Wd[(size_t)(k0 + tid) * NX + k0];
        #pragma unroll
        for (int c = 0; c < LU_NB; c++) a[c] = src[c];
    }
    __syncthreads();

    #pragma unroll
    for (int j = 0; j < LU_NB; j++) {
        if (tid == j) {
            s_piv[j]  = a[j];
            s_pinv    = 1.0 / a[j];
            #pragma unroll
            for (int c = 0; c < LU_NB; c++)
                if (c > j) s_u[c] = a[c];
        }
        __syncthreads();
        if (tid > j && tid < R) {
            double m = a[j] * s_pinv;
            a[j] = m;
            #pragma unroll
            for (int c = 0; c < LU_NB; c++)
                if (c > j) a[c] -= m * s_u[c];
        }
        __syncthreads();
    }

    if (tid < R) {
        double* dst = &g_Wd[(size_t)(k0 + tid) * NX + k0];
        #pragma unroll
        for (int c = 0; c < LU_NB; c++) dst[c] = a[c];
    }

    // pivot logs; one atomic per panel (panels serialize -> deterministic)
    if (tid < 32) {
        double lg = (tid < LU_NB) ? log(fabs(s_piv[tid])) : 0.0;
        #pragma unroll
        for (int o = 16; o; o >>= 1) lg += __shfl_down_sync(0xffffffffu, lg, o);
        if (tid == 0) atomicAdd(&g_logabsdet, lg);
    }
}

// ---------------------------------------------------------------------------
// Merged trsm + trailing update. Block (bx,by) owns the 16x16 A22 tile at
// (r0,c0). It recomputes U12(:,c0 block) = L11^{-1} A12(:,c0 block) locally
// (identical ops in every row-block -> bitwise deterministic), then does
// A22 -= L21 * U12. U12 is NOT written back (never needed again).
// ---------------------------------------------------------------------------
__global__ void __launch_bounds__(256) lu_trail_trsm(int k0) {
    __shared__ double L11[LU_NB][LU_NB + 1];
    __shared__ double U12[LU_NB][LU_NB + 1];
    __shared__ double L21[LU_NB][LU_NB + 1];

    const int tid = threadIdx.x;           // 256
    const int rr = tid >> 4, cc = tid & 15;
    const int r0 = k0 + LU_NB + blockIdx.y * LU_NB;
    const int c0 = k0 + LU_NB + blockIdx.x * LU_NB;

    L11[rr][cc] = g_Wd[(size_t)(k0 + rr) * NX + k0 + cc];
    L21[rr][cc] = g_Wd[(size_t)(r0 + rr) * NX + k0 + cc];
    U12[rr][cc] = g_Wd[(size_t)(k0 + rr) * NX + c0 + cc];
    __syncthreads();

    // local trsm: 16 threads, one column each, column in registers
    if (tid < LU_NB) {
        double u[LU_NB];
        #pragma unroll
        for (int i = 0; i < LU_NB; i++) u[i] = U12[i][tid];
        #pragma unroll
        for (int i = 0; i < LU_NB; i++) {
            double ui = u[i];
            #pragma unroll
            for (int r = i + 1; r < LU_NB; r++) u[r] -= L11[r][i] * ui;
        }
        #pragma unroll
        for (int i = 0; i < LU_NB; i++) U12[i][tid] = u[i];
    }
    __syncthreads();

    double s = 0.0;
    #pragma unroll
    for (int k = 0; k < LU_NB; k++) s += L21[rr][k] * U12[k][cc];
    g_Wd[(size_t)(r0 + rr) * NX + c0 + cc] -= s;
}

__global__ void write_logdet_kernel(float* __restrict__ out_ld) {
    out_ld[threadIdx.x] = (float)((double)NT * g_logabsdet);
}

// ---------------------------------------------------------------------------
// HMMA bf16 GEMM, K = 3*512 concatenated (hi*hi, hi*lo, lo*hi).
// Tile 128x128, 8 warps, BK=32, cp.async double-buffered, fused output roll.
// ---------------------------------------------------------------------------
#define BM 128
#define BN 128
#define SROW 80                 // bytes per smem row (32 bf16 + 8 pad)
#define STAGE_BYTES (128 * SROW)
#define NITER 48                // 3 passes * 16 k-chunks of 32

__global__ void __launch_bounds__(256, 2)
gemm_tc_kernel(float* __restrict__ out) {
    __shared__ __align__(16) char sA[2][STAGE_BYTES];
    __shared__ __align__(16) char sB[2][STAGE_BYTES];

    const int tid  = threadIdx.x;
    const int lane = tid & 31;
    const int wid  = tid >> 5;
    const int wr   = wid >> 2;          // 0..1  (m)
    const int wc   = wid & 3;           // 0..3  (n)

    const int b  = blockIdx.z;
    const int n0 = blockIdx.x * BN;
    const int m0 = blockIdx.y * BM;
    const int T0 = g_T0[b];

    const uint32_t sAu = smem_u32(sA);
    const uint32_t sBu = smem_u32(sB);

    const char* aP[3];
    const char* bP[3];
    {
        const char* ph = (const char*)(g_phi_hi + (size_t)b * NT * NX);
        const char* pl = (const char*)(g_phi_lo + (size_t)b * NT * NX);
        aP[0] = ph; aP[1] = ph; aP[2] = pl;
        bP[0] = (const char*)g_wt_hi; bP[1] = (const char*)g_wt_lo; bP[2] = (const char*)g_wt_hi;
    }

    auto load_iter = [&](int it) {
        int p = it >> 4, c = it & 15, s = it & 1;
        size_t kofs = (size_t)c * 64;
        const char* asrc = aP[p];
        const char* bsrc = bP[p];
        #pragma unroll
        for (int rep = 0; rep < 2; rep++) {
            int idx = tid + rep * 256;          // 0..511
            int row = idx >> 2;
            int q   = idx & 3;
            uint32_t dofs = (uint32_t)(row * SROW + q * 16);
            cp_async16(sAu + s * STAGE_BYTES + dofs,
                       asrc + (size_t)(m0 + row) * 1024 + kofs + q * 16);
            cp_async16(sBu + s * STAGE_BYTES + dofs,
                       bsrc + (size_t)(n0 + row) * 1024 + kofs + q * 16);
        }
        CP_COMMIT();
    };

    float acc[4][4][4];
    #pragma unroll
    for (int i = 0; i < 4; i++)
        #pragma unroll
        for (int j = 0; j < 4; j++)
            #pragma unroll
            for (int q = 0; q < 4; q++) acc[i][j][q] = 0.0f;

    const int lm  = lane & 15;
    const int lk8 = lane >> 4;
    const int bn  = (lane & 7) + ((lane >> 4) << 3);
    const int bk8 = (lane >> 3) & 1;

    const uint32_t aLaneOfs = (uint32_t)((wr * 64 + lm) * SROW + lk8 * 16);
    const uint32_t bLaneOfs = (uint32_t)((wc * 32 + bn) * SROW + bk8 * 16);

    load_iter(0);

    for (int it = 0; it < NITER; it++) {
        int s = it & 1;
        if (it + 1 < NITER) {
            load_iter(it + 1);
            asm volatile("cp.async.wait_group 1;" ::: "memory");
        } else {
            asm volatile("cp.async.wait_group 0;" ::: "memory");
        }
        __syncthreads();

        const uint32_t aStage = sAu + s * STAGE_BYTES + aLaneOfs;
        const uint32_t bStage = sBu + s * STAGE_BYTES + bLaneOfs;

        #pragma unroll
        for (int ks = 0; ks < 2; ks++) {
            uint32_t af[4][4];
            #pragma unroll
            for (int i = 0; i < 4; i++)
                ldsm_x4(af[i], aStage + i * (16 * SROW) + ks * 32);
            uint32_t bf[2][4];
            #pragma unroll
            for (int jp = 0; jp < 2; jp++)
                ldsm_x4(bf[jp], bStage + jp * (16 * SROW) + ks * 32);
            #pragma unroll
            for (int i = 0; i < 4; i++)
                #pragma unroll
                for (int j = 0; j < 4; j++)
                    mma16816(acc[i][j], af[i], &bf[j >> 1][(j & 1) * 2]);
        }
        __syncthreads();
    }

    float* C = out + (size_t)b * NT * NX;
    #pragma unroll
    for (int i = 0; i < 4; i++) {
        int m_lo = m0 + wr * 64 + i * 16 + (lane >> 2);
        int m_hi = m_lo + 8;
        int or_lo = (m_lo - T0 + NT) & (NT - 1);
        int or_hi = (m_hi - T0 + NT) & (NT - 1);
        #pragma unroll
        for (int j = 0; j < 4; j++) {
            int col = n0 + wc * 32 + j * 8 + (lane & 3) * 2;
            *(float2*)(C + (size_t)or_lo * NX + col) = make_float2(acc[i][j][0], acc[i][j][1]);
            *(float2*)(C + (size_t)or_hi * NX + col) = make_float2(acc[i][j][2], acc[i][j][3]);
        }
    }
}

// ---------------------------------------------------------------------------
// Launch. Main stream: argmin(0), prepW(1), prep_phi(2), GEMM(3 <- profiled).
// Side stream (event fork/join, capture-legal): fp64 GENP LU chain + logdet.
// ---------------------------------------------------------------------------
extern "C" void kernel_launch(void* const* d_in, const int* in_sizes, int n_in,
                              void* d_out, int out_size) {
    const float* phi = (const float*)d_in[0];
    const float* W   = (const float*)d_in[1];
    float* out = (float*)d_out;

    static cudaStream_t s_side = nullptr;
    static cudaEvent_t  s_fork = nullptr, s_join = nullptr;
    if (s_side == nullptr) {
        cudaStreamCreateWithFlags(&s_side, cudaStreamNonBlocking);
        cudaEventCreateWithFlags(&s_fork, cudaEventDisableTiming);
        cudaEventCreateWithFlags(&s_join, cudaEventDisableTiming);
    }

    cudaEventRecord(s_fork, 0);
    cudaStreamWaitEvent(s_side, s_fork, 0);

    // ---- main stream ----
    argmin_kernel<<<NB, 32>>>(phi);                       // our launch 0
    {
        dim3 g(NX / 32, NX / 32), blk(32, 32);
        prep_W_bf16<<<g, blk>>>(W);                       // our launch 1
    }
    prep_phi_kernel<<<NB * NT, 128>>>(phi);               // our launch 2
    {
        dim3 grid(NX / BN, NT / BM, NB);
        gemm_tc_kernel<<<grid, 256>>>(out);               // our launch 3 (ncu target)
    }

    // ---- side stream: logdet chain ----
    convert_Wd<<<(NX * NX + 255) / 256, 256, 0, s_side>>>(W);
    for (int p = 0; p < NX / LU_NB; p++) {
        int k0 = p * LU_NB;
        lu_panel_genp<<<1, 512, 0, s_side>>>(k0);
        int cols2 = NX - k0 - LU_NB;
        if (cols2 > 0) {
            dim3 g(cols2 / LU_NB, cols2 / LU_NB);
            lu_trail_trsm<<<g, 256, 0, s_side>>>(k0);
        }
    }
    write_logdet_kernel<<<1, NB, 0, s_side>>>(out + (out_size - NB));

    cudaEventRecord(s_join, s_side);
    cudaStreamWaitEvent(0, s_join, 0);
}

// round 10
// speedup vs baseline: 2.7514x; 1.0814x over previous
#include <cuda_runtime.h>
#include <cuda_bf16.h>
#include <math.h>
#include <stdint.h>

#define NB  256
#define NT  512
#define NX  512

// ---------------------------------------------------------------------------
// Device scratch (static; no allocations anywhere)
// ---------------------------------------------------------------------------
__device__ __nv_bfloat16 g_phi_hi[(size_t)NB * NT * NX];  // rolled phi, hi half
__device__ __nv_bfloat16 g_phi_lo[(size_t)NB * NT * NX];  // rolled phi, lo half
__device__ __nv_bfloat16 g_wt_hi[(size_t)NX * NX];        // W^T hi  [y][x]
__device__ __nv_bfloat16 g_wt_lo[(size_t)NX * NX];        // W^T lo  [y][x]
__device__ int    g_T0[NB];
__device__ double g_Wd[NX * NX];
__device__ double g_logabsdet;

// ---------------------------------------------------------------------------
// PTX helpers (sm_80-era, safe on compute_103)
// ---------------------------------------------------------------------------
__device__ __forceinline__ uint32_t smem_u32(const void* p) {
    uint32_t a;
    asm("{ .reg .u64 t; cvta.to.shared.u64 t, %1; cvt.u32.u64 %0, t; }" : "=r"(a) : "l"(p));
    return a;
}
__device__ __forceinline__ void cp_async16(uint32_t dst, const void* src) {
    asm volatile("cp.async.cg.shared.global [%0], [%1], 16;" :: "r"(dst), "l"(src) : "memory");
}
#define CP_COMMIT() asm volatile("cp.async.commit_group;" ::: "memory")

__device__ __forceinline__ void ldsm_x4(uint32_t* r, uint32_t addr) {
    asm volatile("ldmatrix.sync.aligned.m8n8.x4.shared.b16 {%0,%1,%2,%3}, [%4];"
        : "=r"(r[0]), "=r"(r[1]), "=r"(r[2]), "=r"(r[3]) : "r"(addr));
}
__device__ __forceinline__ void mma16816(float* c, const uint32_t* a, const uint32_t* b) {
    asm volatile("mma.sync.aligned.m16n8k16.row.col.f32.bf16.bf16.f32 "
        "{%0,%1,%2,%3}, {%4,%5,%6,%7}, {%8,%9}, {%0,%1,%2,%3};"
        : "+f"(c[0]), "+f"(c[1]), "+f"(c[2]), "+f"(c[3])
        : "r"(a[0]), "r"(a[1]), "r"(a[2]), "r"(a[3]), "r"(b[0]), "r"(b[1]));
}

// ---------------------------------------------------------------------------
// argmin -> T0 per sample
// ---------------------------------------------------------------------------
__global__ void argmin_kernel(const float* __restrict__ phi) {
    int b = blockIdx.x, lane = threadIdx.x;
    const float* p = phi + (size_t)b * NT * NX;
    float bv0 = 1e38f; int bi0 = 0;
    float bv1 = 1e38f; int bi1 = 0;
    for (int t = lane; t < NT; t += 32) {
        float v0 = fabsf(p[(size_t)t * NX + 0]);
        float v1 = fabsf(p[(size_t)t * NX + 1]);
        if (v0 < bv0) { bv0 = v0; bi0 = t; }
        if (v1 < bv1) { bv1 = v1; bi1 = t; }
    }
    #pragma unroll
    for (int o = 16; o; o >>= 1) {
        float ov = __shfl_down_sync(0xffffffffu, bv0, o);
        int   oi = __shfl_down_sync(0xffffffffu, bi0, o);
        if (ov < bv0 || (ov == bv0 && oi < bi0)) { bv0 = ov; bi0 = oi; }
        ov = __shfl_down_sync(0xffffffffu, bv1, o);
        oi = __shfl_down_sync(0xffffffffu, bi1, o);
        if (ov < bv1 || (ov == bv1 && oi < bi1)) { bv1 = ov; bi1 = oi; }
    }
    if (lane == 0) g_T0[b] = (bi0 > bi1) ? bi1 : bi0;
}

// ---------------------------------------------------------------------------
// W prep (main stream): transpose-split to bf16 hi/lo (GEMM B operand)
// ---------------------------------------------------------------------------
__global__ void prep_W_bf16(const float* __restrict__ W) {
    __shared__ float t[32][33];
    int tx = threadIdx.x, ty = threadIdx.y;
    int r = blockIdx.y * 32 + ty, c = blockIdx.x * 32 + tx;
    t[ty][tx] = W[(size_t)r * NX + c];
    __syncthreads();
    int rr = blockIdx.x * 32 + ty, cc = blockIdx.y * 32 + tx;
    float v = t[tx][ty];
    __nv_bfloat16 hi = __float2bfloat16(v);
    __nv_bfloat16 lo = __float2bfloat16(v - __bfloat162float(hi));
    g_wt_hi[(size_t)rr * NX + cc] = hi;
    g_wt_lo[(size_t)rr * NX + cc] = lo;
}

// ---------------------------------------------------------------------------
// W prep (side stream): fp64 copy + logdet reset
// ---------------------------------------------------------------------------
__global__ void convert_Wd(const float* __restrict__ W) {
    int i = blockIdx.x * blockDim.x + threadIdx.x;
    if (i < NX * NX) g_Wd[i] = (double)W[i];
    if (i == 0) g_logabsdet = 0.0;
}

// ---------------------------------------------------------------------------
// phi prep: roll along x by +T0 and split to bf16 hi/lo.
// ---------------------------------------------------------------------------
__global__ void prep_phi_kernel(const float* __restrict__ phi) {
    int row = blockIdx.x;                 // b*512 + t
    int b = row >> 9;
    int T0 = g_T0[b];
    const float* src = phi + (size_t)row * NX;
    __nv_bfloat16* dh = g_phi_hi + (size_t)row * NX;
    __nv_bfloat16* dl = g_phi_lo + (size_t)row * NX;
    for (int u = threadIdx.x; u < NX; u += 128) {
        float f = src[(u - T0) & (NX - 1)];
        __nv_bfloat16 hi = __float2bfloat16(f);
        __nv_bfloat16 lo = __float2bfloat16(f - __bfloat162float(hi));
        dh[u] = hi; dl[u] = lo;
    }
}

// ---------------------------------------------------------------------------
// Fully distributed GENP LU step (nb=16). NO central panel kernel.
// Block (bx,by) owns the 16x16 A22 tile at (r0,c0). It:
//   1. locally refactors the 16x16 diagonal block D (redundant, deterministic)
//   2. solves its L21 row-block = A21 * U11^{-1}  (warp1, 16 threads)
//      and its U12 col-block = L11^{-1} * A12    (warp0, 16 threads)
//   3. A22 -= L21 * U12
// Nothing except A22 is written back (cols<k0+16 / rows<k0+16 are dead).
// Block (0,0) also accumulates sum(log|U11_ii|) for this step.
// ---------------------------------------------------------------------------
#define LU_NB 16

__global__ void __launch_bounds__(256) lu_step(int k0) {
    __shared__ double D[16][17];     // diag block -> L11\U11
    __shared__ double U12[16][17];   // A12 -> U12
    __shared__ double L21[16][17];   // A21 -> L21
    __shared__ double s_uinv[16];

    const int tid = threadIdx.x;           // 256
    const int rr = tid >> 4, cc = tid & 15;
    const int r0 = k0 + 16 + blockIdx.y * 16;
    const int c0 = k0 + 16 + blockIdx.x * 16;

    D[rr][cc]   = g_Wd[(size_t)(k0 + rr) * NX + k0 + cc];
    L21[rr][cc] = g_Wd[(size_t)(r0 + rr) * NX + k0 + cc];
    U12[rr][cc] = g_Wd[(size_t)(k0 + rr) * NX + c0 + cc];
    __syncthreads();

    // 1. GENP factor of D, threads 0..15 (lanes 0-15 of warp 0), row-parallel
    if (tid < 16) {
        const int r = tid;
        #pragma unroll
        for (int j = 0; j < 15; j++) {
            if (r > j) {
                double m = D[r][j] / D[j][j];
                D[r][j] = m;
                #pragma unroll
                for (int c = 0; c < 16; c++)
                    if (c > j) D[r][c] -= m * D[j][c];
            }
            __syncwarp(0x0000FFFFu);
        }
        s_uinv[r] = 1.0 / D[r][r];
    }
    __syncthreads();

    // 2. local trsms, two independent 16-thread groups in different warps
    if (tid < 16) {
        // U12 column solve: L11 (unit lower, strict part of D) forward-sub
        const int c = tid;
        double u[16];
        #pragma unroll
        for (int i = 0; i < 16; i++) u[i] = U12[i][c];
        #pragma unroll
        for (int i = 0; i < 16; i++) {
            double ui = u[i];
            #pragma unroll
            for (int r = i + 1; r < 16; r++) u[r] -= D[r][i] * ui;
        }
        #pragma unroll
        for (int i = 0; i < 16; i++) U12[i][c] = u[i];
    } else if (tid >= 32 && tid < 48) {
        // L21 row solve: x * U11 = a  (U11 = upper incl diag of D)
        const int r = tid - 32;
        double x[16];
        #pragma unroll
        for (int i = 0; i < 16; i++) x[i] = L21[r][i];
        #pragma unroll
        for (int i = 0; i < 16; i++) {
            double xi = x[i] * s_uinv[i];
            x[i] = xi;
            #pragma unroll
            for (int c = i + 1; c < 16; c++) x[c] -= xi * D[i][c];
        }
        #pragma unroll
        for (int i = 0; i < 16; i++) L21[r][i] = x[i];
    }
    __syncthreads();

    // 3. A22 -= L21 * U12
    double s = 0.0;
    #pragma unroll
    for (int k = 0; k < 16; k++) s += L21[rr][k] * U12[k][cc];
    g_Wd[(size_t)(r0 + rr) * NX + c0 + cc] -= s;

    // logs for this step (one block; one atomic per step, stream-ordered)
    if (blockIdx.x == 0 && blockIdx.y == 0 && tid < 32) {
        double lg = (tid < 16) ? log(fabs(D[tid][tid])) : 0.0;
        #pragma unroll
        for (int o = 16; o; o >>= 1) lg += __shfl_down_sync(0xffffffffu, lg, o);
        if (tid == 0) atomicAdd(&g_logabsdet, lg);
    }
}

// Final 16x16 diagonal block: factor + logs only (no trailing).
__global__ void __launch_bounds__(256) lu_last(int k0) {
    __shared__ double D[16][17];
    const int tid = threadIdx.x;
    const int rr = tid >> 4, cc = tid & 15;
    D[rr][cc] = g_Wd[(size_t)(k0 + rr) * NX + k0 + cc];
    __syncthreads();
    if (tid < 16) {
        const int r = tid;
        #pragma unroll
        for (int j = 0; j < 15; j++) {
            if (r > j) {
                double m = D[r][j] / D[j][j];
                #pragma unroll
                for (int c = 0; c < 16; c++)
                    if (c > j) D[r][c] -= m * D[j][c];
            }
            __syncwarp(0x0000FFFFu);
        }
    }
    __syncthreads();
    if (tid < 32) {
        double lg = (tid < 16) ? log(fabs(D[tid][tid])) : 0.0;
        #pragma unroll
        for (int o = 16; o; o >>= 1) lg += __shfl_down_sync(0xffffffffu, lg, o);
        if (tid == 0) atomicAdd(&g_logabsdet, lg);
    }
}

__global__ void write_logdet_kernel(float* __restrict__ out_ld) {
    out_ld[threadIdx.x] = (float)((double)NT * g_logabsdet);
}

// ---------------------------------------------------------------------------
// HMMA bf16 GEMM, K = 3*512 concatenated (hi*hi, hi*lo, lo*hi).
// Tile 128x128, 8 warps, BK=32, cp.async double-buffered, fused output roll.
// ---------------------------------------------------------------------------
#define BM 128
#define BN 128
#define SROW 80                 // bytes per smem row (32 bf16 + 8 pad)
#define STAGE_BYTES (128 * SROW)
#define NITER 48                // 3 passes * 16 k-chunks of 32

__global__ void __launch_bounds__(256, 2)
gemm_tc_kernel(float* __restrict__ out) {
    __shared__ __align__(16) char sA[2][STAGE_BYTES];
    __shared__ __align__(16) char sB[2][STAGE_BYTES];

    const int tid  = threadIdx.x;
    const int lane = tid & 31;
    const int wid  = tid >> 5;
    const int wr   = wid >> 2;          // 0..1  (m)
    const int wc   = wid & 3;           // 0..3  (n)

    const int b  = blockIdx.z;
    const int n0 = blockIdx.x * BN;
    const int m0 = blockIdx.y * BM;
    const int T0 = g_T0[b];

    const uint32_t sAu = smem_u32(sA);
    const uint32_t sBu = smem_u32(sB);

    const char* aP[3];
    const char* bP[3];
    {
        const char* ph = (const char*)(g_phi_hi + (size_t)b * NT * NX);
        const char* pl = (const char*)(g_phi_lo + (size_t)b * NT * NX);
        aP[0] = ph; aP[1] = ph; aP[2] = pl;
        bP[0] = (const char*)g_wt_hi; bP[1] = (const char*)g_wt_lo; bP[2] = (const char*)g_wt_hi;
    }

    auto load_iter = [&](int it) {
        int p = it >> 4, c = it & 15, s = it & 1;
        size_t kofs = (size_t)c * 64;
        const char* asrc = aP[p];
        const char* bsrc = bP[p];
        #pragma unroll
        for (int rep = 0; rep < 2; rep++) {
            int idx = tid + rep * 256;          // 0..511
            int row = idx >> 2;
            int q   = idx & 3;
            uint32_t dofs = (uint32_t)(row * SROW + q * 16);
            cp_async16(sAu + s * STAGE_BYTES + dofs,
                       asrc + (size_t)(m0 + row) * 1024 + kofs + q * 16);
            cp_async16(sBu + s * STAGE_BYTES + dofs,
                       bsrc + (size_t)(n0 + row) * 1024 + kofs + q * 16);
        }
        CP_COMMIT();
    };

    float acc[4][4][4];
    #pragma unroll
    for (int i = 0; i < 4; i++)
        #pragma unroll
        for (int j = 0; j < 4; j++)
            #pragma unroll
            for (int q = 0; q < 4; q++) acc[i][j][q] = 0.0f;

    const int lm  = lane & 15;
    const int lk8 = lane >> 4;
    const int bn  = (lane & 7) + ((lane >> 4) << 3);
    const int bk8 = (lane >> 3) & 1;

    const uint32_t aLaneOfs = (uint32_t)((wr * 64 + lm) * SROW + lk8 * 16);
    const uint32_t bLaneOfs = (uint32_t)((wc * 32 + bn) * SROW + bk8 * 16);

    load_iter(0);

    for (int it = 0; it < NITER; it++) {
        int s = it & 1;
        if (it + 1 < NITER) {
            load_iter(it + 1);
            asm volatile("cp.async.wait_group 1;" ::: "memory");
        } else {
            asm volatile("cp.async.wait_group 0;" ::: "memory");
        }
        __syncthreads();

        const uint32_t aStage = sAu + s * STAGE_BYTES + aLaneOfs;
        const uint32_t bStage = sBu + s * STAGE_BYTES + bLaneOfs;

        #pragma unroll
        for (int ks = 0; ks < 2; ks++) {
            uint32_t af[4][4];
            #pragma unroll
            for (int i = 0; i < 4; i++)
                ldsm_x4(af[i], aStage + i * (16 * SROW) + ks * 32);
            uint32_t bf[2][4];
            #pragma unroll
            for (int jp = 0; jp < 2; jp++)
                ldsm_x4(bf[jp], bStage + jp * (16 * SROW) + ks * 32);
            #pragma unroll
            for (int i = 0; i < 4; i++)
                #pragma unroll
                for (int j = 0; j < 4; j++)
                    mma16816(acc[i][j], af[i], &bf[j >> 1][(j & 1) * 2]);
        }
        __syncthreads();
    }

    float* C = out + (size_t)b * NT * NX;
    #pragma unroll
    for (int i = 0; i < 4; i++) {
        int m_lo = m0 + wr * 64 + i * 16 + (lane >> 2);
        int m_hi = m_lo + 8;
        int or_lo = (m_lo - T0 + NT) & (NT - 1);
        int or_hi = (m_hi - T0 + NT) & (NT - 1);
        #pragma unroll
        for (int j = 0; j < 4; j++) {
            int col = n0 + wc * 32 + j * 8 + (lane & 3) * 2;
            *(float2*)(C + (size_t)or_lo * NX + col) = make_float2(acc[i][j][0], acc[i][j][1]);
            *(float2*)(C + (size_t)or_hi * NX + col) = make_float2(acc[i][j][2], acc[i][j][3]);
        }
    }
}

// ---------------------------------------------------------------------------
// Launch. Main stream: argmin(0), prepW(1), prep_phi(2), GEMM(3 <- profiled).
// Side stream (event fork/join): distributed GENP LU chain + logdet.
// ---------------------------------------------------------------------------
extern "C" void kernel_launch(void* const* d_in, const int* in_sizes, int n_in,
                              void* d_out, int out_size) {
    const float* phi = (const float*)d_in[0];
    const float* W   = (const float*)d_in[1];
    float* out = (float*)d_out;

    static cudaStream_t s_side = nullptr;
    static cudaEvent_t  s_fork = nullptr, s_join = nullptr;
    if (s_side == nullptr) {
        cudaStreamCreateWithFlags(&s_side, cudaStreamNonBlocking);
        cudaEventCreateWithFlags(&s_fork, cudaEventDisableTiming);
        cudaEventCreateWithFlags(&s_join, cudaEventDisableTiming);
    }

    cudaEventRecord(s_fork, 0);
    cudaStreamWaitEvent(s_side, s_fork, 0);

    // ---- main stream ----
    argmin_kernel<<<NB, 32>>>(phi);                       // our launch 0
    {
        dim3 g(NX / 32, NX / 32), blk(32, 32);
        prep_W_bf16<<<g, blk>>>(W);                       // our launch 1
    }
    prep_phi_kernel<<<NB * NT, 128>>>(phi);               // our launch 2
    {
        dim3 grid(NX / BN, NT / BM, NB);
        gemm_tc_kernel<<<grid, 256>>>(out);               // our launch 3 (ncu target)
    }

    // ---- side stream: logdet chain (fully distributed LU) ----
    convert_Wd<<<(NX * NX + 255) / 256, 256, 0, s_side>>>(W);
    for (int p = 0; p < NX / LU_NB - 1; p++) {
        int k0 = p * LU_NB;
        int nblk = (NX - k0 - LU_NB) / LU_NB;             // 31 .. 1
        dim3 g(nblk, nblk);
        lu_step<<<g, 256, 0, s_side>>>(k0);
    }
    lu_last<<<1, 256, 0, s_side>>>(NX - LU_NB);
    write_logdet_kernel<<<1, NB, 0, s_side>>>(out + (out_size - NB));

    cudaEventRecord(s_join, s_side);
    cudaStreamWaitEvent(0, s_join, 0);
}

// round 12
// speedup vs baseline: 4.2201x; 1.5338x over previous
#include <cuda_runtime.h>
#include <cuda_bf16.h>
#include <math.h>
#include <stdint.h>

#define NB  256
#define NT  512
#define NX  512

// ---------------------------------------------------------------------------
// Device scratch (static; no allocations anywhere)
// ---------------------------------------------------------------------------
__device__ __nv_bfloat16 g_phi_hi[(size_t)NB * NT * NX];  // rolled phi, hi half
__device__ __nv_bfloat16 g_phi_lo[(size_t)NB * NT * NX];  // rolled phi, lo half
__device__ __nv_bfloat16 g_wt_hi[(size_t)NX * NX];        // W^T hi  [y][x]
__device__ __nv_bfloat16 g_wt_lo[(size_t)NX * NX];        // W^T lo  [y][x]
__device__ int    g_T0[NB];
__device__ float  g_Wf[NX * NX];                          // fp32 LU workspace
__device__ double g_logabsdet;

// ---------------------------------------------------------------------------
// PTX helpers (sm_80-era, safe on compute_103)
// ---------------------------------------------------------------------------
__device__ __forceinline__ uint32_t smem_u32(const void* p) {
    uint32_t a;
    asm("{ .reg .u64 t; cvta.to.shared.u64 t, %1; cvt.u32.u64 %0, t; }" : "=r"(a) : "l"(p));
    return a;
}
__device__ __forceinline__ void cp_async16(uint32_t dst, const void* src) {
    asm volatile("cp.async.cg.shared.global [%0], [%1], 16;" :: "r"(dst), "l"(src) : "memory");
}
#define CP_COMMIT() asm volatile("cp.async.commit_group;" ::: "memory")

__device__ __forceinline__ void ldsm_x4(uint32_t* r, uint32_t addr) {
    asm volatile("ldmatrix.sync.aligned.m8n8.x4.shared.b16 {%0,%1,%2,%3}, [%4];"
        : "=r"(r[0]), "=r"(r[1]), "=r"(r[2]), "=r"(r[3]) : "r"(addr));
}
__device__ __forceinline__ void mma16816(float* c, const uint32_t* a, const uint32_t* b) {
    asm volatile("mma.sync.aligned.m16n8k16.row.col.f32.bf16.bf16.f32 "
        "{%0,%1,%2,%3}, {%4,%5,%6,%7}, {%8,%9}, {%0,%1,%2,%3};"
        : "+f"(c[0]), "+f"(c[1]), "+f"(c[2]), "+f"(c[3])
        : "r"(a[0]), "r"(a[1]), "r"(a[2]), "r"(a[3]), "r"(b[0]), "r"(b[1]));
}

// ---------------------------------------------------------------------------
// argmin -> T0 per sample
// ---------------------------------------------------------------------------
__global__ void argmin_kernel(const float* __restrict__ phi) {
    int b = blockIdx.x, lane = threadIdx.x;
    const float* p = phi + (size_t)b * NT * NX;
    float bv0 = 1e38f; int bi0 = 0;
    float bv1 = 1e38f; int bi1 = 0;
    for (int t = lane; t < NT; t += 32) {
        float v0 = fabsf(p[(size_t)t * NX + 0]);
        float v1 = fabsf(p[(size_t)t * NX + 1]);
        if (v0 < bv0) { bv0 = v0; bi0 = t; }
        if (v1 < bv1) { bv1 = v1; bi1 = t; }
    }
    #pragma unroll
    for (int o = 16; o; o >>= 1) {
        float ov = __shfl_down_sync(0xffffffffu, bv0, o);
        int   oi = __shfl_down_sync(0xffffffffu, bi0, o);
        if (ov < bv0 || (ov == bv0 && oi < bi0)) { bv0 = ov; bi0 = oi; }
        ov = __shfl_down_sync(0xffffffffu, bv1, o);
        oi = __shfl_down_sync(0xffffffffu, bi1, o);
        if (ov < bv1 || (ov == bv1 && oi < bi1)) { bv1 = ov; bi1 = oi; }
    }
    if (lane == 0) g_T0[b] = (bi0 > bi1) ? bi1 : bi0;
}

// ---------------------------------------------------------------------------
// W prep (main stream): transpose-split to bf16 hi/lo (GEMM B operand)
// ---------------------------------------------------------------------------
__global__ void prep_W_bf16(const float* __restrict__ W) {
    __shared__ float t[32][33];
    int tx = threadIdx.x, ty = threadIdx.y;
    int r = blockIdx.y * 32 + ty, c = blockIdx.x * 32 + tx;
    t[ty][tx] = W[(size_t)r * NX + c];
    __syncthreads();
    int rr = blockIdx.x * 32 + ty, cc = blockIdx.y * 32 + tx;
    float v = t[tx][ty];
    __nv_bfloat16 hi = __float2bfloat16(v);
    __nv_bfloat16 lo = __float2bfloat16(v - __bfloat162float(hi));
    g_wt_hi[(size_t)rr * NX + cc] = hi;
    g_wt_lo[(size_t)rr * NX + cc] = lo;
}

// ---------------------------------------------------------------------------
// W prep (side stream): fp32 copy + logdet reset
// ---------------------------------------------------------------------------
__global__ void copy_Wf(const float* __restrict__ W) {
    int i = blockIdx.x * blockDim.x + threadIdx.x;
    if (i < NX * NX) g_Wf[i] = W[i];
    if (i == 0) g_logabsdet = 0.0;
}

// ---------------------------------------------------------------------------
// phi prep: roll along x by +T0 and split to bf16 hi/lo.
// ---------------------------------------------------------------------------
__global__ void prep_phi_kernel(const float* __restrict__ phi) {
    int row = blockIdx.x;                 // b*512 + t
    int b = row >> 9;
    int T0 = g_T0[b];
    const float* src = phi + (size_t)row * NX;
    __nv_bfloat16* dh = g_phi_hi + (size_t)row * NX;
    __nv_bfloat16* dl = g_phi_lo + (size_t)row * NX;
    for (int u = threadIdx.x; u < NX; u += 128) {
        float f = src[(u - T0) & (NX - 1)];
        __nv_bfloat16 hi = __float2bfloat16(f);
        __nv_bfloat16 lo = __float2bfloat16(f - __bfloat162float(hi));
        dh[u] = hi; dl[u] = lo;
    }
}

// ---------------------------------------------------------------------------
// Fully distributed fp32 GENP LU step (nb=32). Block (bx,by) owns the 32x32
// A22 tile at (r0,c0):
//   1. locally refactors the 32x32 diagonal block D (redundant, deterministic)
//   2. solves its U12 col-block (warp0) and L21 row-block (warp1)
//   3. A22 -= L21 * U12
// Only A22 is written. Smem rows padded to 36 floats (144 B = 9*16) so the
// float4 accesses at [rr][c4] are 16B-aligned (33-float pad was the R11 bug).
// ---------------------------------------------------------------------------
#define LU_NB 32
#define LPAD  36

__global__ void __launch_bounds__(256) lu_step(int k0) {
    __shared__ float D[32][LPAD];
    __shared__ float U12[32][LPAD];
    __shared__ float L21[32][LPAD];
    __shared__ float s_uinv[32];

    const int tid = threadIdx.x;            // 256
    const int rr  = tid >> 3;               // 0..31
    const int c4  = (tid & 7) * 4;          // 0..28 step 4
    const int r0 = k0 + 32 + blockIdx.y * 32;
    const int c0 = k0 + 32 + blockIdx.x * 32;

    {
        float4 d  = *(const float4*)&g_Wf[(size_t)(k0 + rr) * NX + k0 + c4];
        float4 l  = *(const float4*)&g_Wf[(size_t)(r0 + rr) * NX + k0 + c4];
        float4 u  = *(const float4*)&g_Wf[(size_t)(k0 + rr) * NX + c0 + c4];
        *(float4*)&D[rr][c4]   = d;
        *(float4*)&L21[rr][c4] = l;
        *(float4*)&U12[rr][c4] = u;
    }
    __syncthreads();

    // 1. GENP factor of D: warp 0, one row per lane, 31 serial steps
    if (tid < 32) {
        const int r = tid;
        #pragma unroll
        for (int j = 0; j < 31; j++) {
            if (r > j) {
                float m = D[r][j] / D[j][j];
                D[r][j] = m;
                #pragma unroll
                for (int c = 0; c < 32; c++)
                    if (c > j) D[r][c] -= m * D[j][c];
            }
            __syncwarp();
        }
        s_uinv[r] = 1.0f / D[r][r];
    }
    __syncthreads();

    // 2. local trsms: warp0 solves U12 columns, warp1 solves L21 rows
    if (tid < 32) {
        const int c = tid;
        float u[32];
        #pragma unroll
        for (int i = 0; i < 32; i++) u[i] = U12[i][c];
        #pragma unroll
        for (int i = 0; i < 32; i++) {
            float ui = u[i];
            #pragma unroll
            for (int r = i + 1; r < 32; r++) u[r] -= D[r][i] * ui;
        }
        #pragma unroll
        for (int i = 0; i < 32; i++) U12[i][c] = u[i];
    } else if (tid < 64) {
        const int r = tid - 32;
        float x[32];
        #pragma unroll
        for (int i = 0; i < 32; i++) x[i] = L21[r][i];
        #pragma unroll
        for (int i = 0; i < 32; i++) {
            float xi = x[i] * s_uinv[i];
            x[i] = xi;
            #pragma unroll
            for (int c = i + 1; c < 32; c++) x[c] -= xi * D[i][c];
        }
        #pragma unroll
        for (int i = 0; i < 32; i++) L21[r][i] = x[i];
    }
    __syncthreads();

    // 3. A22 -= L21 * U12  (each thread: 1x4 outputs)
    float s0 = 0.f, s1 = 0.f, s2 = 0.f, s3 = 0.f;
    #pragma unroll
    for (int k = 0; k < 32; k++) {
        float l = L21[rr][k];
        s0 += l * U12[k][c4 + 0];
        s1 += l * U12[k][c4 + 1];
        s2 += l * U12[k][c4 + 2];
        s3 += l * U12[k][c4 + 3];
    }
    float4* dst = (float4*)&g_Wf[(size_t)(r0 + rr) * NX + c0 + c4];
    float4 old = *dst;
    old.x -= s0; old.y -= s1; old.z -= s2; old.w -= s3;
    *dst = old;

    // logs for this step (block (0,0); one atomic per step, stream-ordered)
    if (blockIdx.x == 0 && blockIdx.y == 0 && tid < 32) {
        double lg = log(fabs((double)D[tid][tid]));
        #pragma unroll
        for (int o = 16; o; o >>= 1) lg += __shfl_down_sync(0xffffffffu, lg, o);
        if (tid == 0) atomicAdd(&g_logabsdet, lg);
    }
}

// Final 32x32 diagonal block: factor + logs only.
__global__ void __launch_bounds__(256) lu_last(int k0) {
    __shared__ float D[32][LPAD];
    const int tid = threadIdx.x;
    const int rr = tid >> 3, c4 = (tid & 7) * 4;
    *(float4*)&D[rr][c4] = *(const float4*)&g_Wf[(size_t)(k0 + rr) * NX + k0 + c4];
    __syncthreads();
    if (tid < 32) {
        const int r = tid;
        #pragma unroll
        for (int j = 0; j < 31; j++) {
            if (r > j) {
                float m = D[r][j] / D[j][j];
                #pragma unroll
                for (int c = 0; c < 32; c++)
                    if (c > j) D[r][c] -= m * D[j][c];
            }
            __syncwarp();
        }
    }
    __syncthreads();
    if (tid < 32) {
        double lg = log(fabs((double)D[tid][tid]));
        #pragma unroll
        for (int o = 16; o; o >>= 1) lg += __shfl_down_sync(0xffffffffu, lg, o);
        if (tid == 0) atomicAdd(&g_logabsdet, lg);
    }
}

__global__ void write_logdet_kernel(float* __restrict__ out_ld) {
    out_ld[threadIdx.x] = (float)((double)NT * g_logabsdet);
}

// ---------------------------------------------------------------------------
// HMMA bf16 GEMM, K = 3*512 concatenated (hi*hi, hi*lo, lo*hi).
// Tile 128x128, 8 warps, BK=32, cp.async double-buffered, fused output roll.
// ---------------------------------------------------------------------------
#define BM 128
#define BN 128
#define SROW 80                 // bytes per smem row (32 bf16 + 8 pad)
#define STAGE_BYTES (128 * SROW)
#define NITER 48                // 3 passes * 16 k-chunks of 32

__global__ void __launch_bounds__(256, 2)
gemm_tc_kernel(float* __restrict__ out) {
    __shared__ __align__(16) char sA[2][STAGE_BYTES];
    __shared__ __align__(16) char sB[2][STAGE_BYTES];

    const int tid  = threadIdx.x;
    const int lane = tid & 31;
    const int wid  = tid >> 5;
    const int wr   = wid >> 2;          // 0..1  (m)
    const int wc   = wid & 3;           // 0..3  (n)

    const int b  = blockIdx.z;
    const int n0 = blockIdx.x * BN;
    const int m0 = blockIdx.y * BM;
    const int T0 = g_T0[b];

    const uint32_t sAu = smem_u32(sA);
    const uint32_t sBu = smem_u32(sB);

    const char* aP[3];
    const char* bP[3];
    {
        const char* ph = (const char*)(g_phi_hi + (size_t)b * NT * NX);
        const char* pl = (const char*)(g_phi_lo + (size_t)b * NT * NX);
        aP[0] = ph; aP[1] = ph; aP[2] = pl;
        bP[0] = (const char*)g_wt_hi; bP[1] = (const char*)g_wt_lo; bP[2] = (const char*)g_wt_hi;
    }

    auto load_iter = [&](int it) {
        int p = it >> 4, c = it & 15, s = it & 1;
        size_t kofs = (size_t)c * 64;
        const char* asrc = aP[p];
        const char* bsrc = bP[p];
        #pragma unroll
        for (int rep = 0; rep < 2; rep++) {
            int idx = tid + rep * 256;          // 0..511
            int row = idx >> 2;
            int q   = idx & 3;
            uint32_t dofs = (uint32_t)(row * SROW + q * 16);
            cp_async16(sAu + s * STAGE_BYTES + dofs,
                       asrc + (size_t)(m0 + row) * 1024 + kofs + q * 16);
            cp_async16(sBu + s * STAGE_BYTES + dofs,
                       bsrc + (size_t)(n0 + row) * 1024 + kofs + q * 16);
        }
        CP_COMMIT();
    };

    float acc[4][4][4];
    #pragma unroll
    for (int i = 0; i < 4; i++)
        #pragma unroll
        for (int j = 0; j < 4; j++)
            #pragma unroll
            for (int q = 0; q < 4; q++) acc[i][j][q] = 0.0f;

    const int lm  = lane & 15;
    const int lk8 = lane >> 4;
    const int bn  = (lane & 7) + ((lane >> 4) << 3);
    const int bk8 = (lane >> 3) & 1;

    const uint32_t aLaneOfs = (uint32_t)((wr * 64 + lm) * SROW + lk8 * 16);
    const uint32_t bLaneOfs = (uint32_t)((wc * 32 + bn) * SROW + bk8 * 16);

    load_iter(0);

    for (int it = 0; it < NITER; it++) {
        int s = it & 1;
        if (it + 1 < NITER) {
            load_iter(it + 1);
            asm volatile("cp.async.wait_group 1;" ::: "memory");
        } else {
            asm volatile("cp.async.wait_group 0;" ::: "memory");
        }
        __syncthreads();

        const uint32_t aStage = sAu + s * STAGE_BYTES + aLaneOfs;
        const uint32_t bStage = sBu + s * STAGE_BYTES + bLaneOfs;

        #pragma unroll
        for (int ks = 0; ks < 2; ks++) {
            uint32_t af[4][4];
            #pragma unroll
            for (int i = 0; i < 4; i++)
                ldsm_x4(af[i], aStage + i * (16 * SROW) + ks * 32);
            uint32_t bf[2][4];
            #pragma unroll
            for (int jp = 0; jp < 2; jp++)
                ldsm_x4(bf[jp], bStage + jp * (16 * SROW) + ks * 32);
            #pragma unroll
            for (int i = 0; i < 4; i++)
                #pragma unroll
                for (int j = 0; j < 4; j++)
                    mma16816(acc[i][j], af[i], &bf[j >> 1][(j & 1) * 2]);
        }
        __syncthreads();
    }

    float* C = out + (size_t)b * NT * NX;
    #pragma unroll
    for (int i = 0; i < 4; i++) {
        int m_lo = m0 + wr * 64 + i * 16 + (lane >> 2);
        int m_hi = m_lo + 8;
        int or_lo = (m_lo - T0 + NT) & (NT - 1);
        int or_hi = (m_hi - T0 + NT) & (NT - 1);
        #pragma unroll
        for (int j = 0; j < 4; j++) {
            int col = n0 + wc * 32 + j * 8 + (lane & 3) * 2;
            *(float2*)(C + (size_t)or_lo * NX + col) = make_float2(acc[i][j][0], acc[i][j][1]);
            *(float2*)(C + (size_t)or_hi * NX + col) = make_float2(acc[i][j][2], acc[i][j][3]);
        }
    }
}

// ---------------------------------------------------------------------------
// Launch. Main stream: argmin(0), prepW(1), prep_phi(2), GEMM(3 <- profiled).
// Side stream (event fork/join): fp32 distributed GENP LU chain + logdet.
// ---------------------------------------------------------------------------
extern "C" void kernel_launch(void* const* d_in, const int* in_sizes, int n_in,
                              void* d_out, int out_size) {
    const float* phi = (const float*)d_in[0];
    const float* W   = (const float*)d_in[1];
    float* out = (float*)d_out;

    static cudaStream_t s_side = nullptr;
    static cudaEvent_t  s_fork = nullptr, s_join = nullptr;
    if (s_side == nullptr) {
        cudaStreamCreateWithFlags(&s_side, cudaStreamNonBlocking);
        cudaEventCreateWithFlags(&s_fork, cudaEventDisableTiming);
        cudaEventCreateWithFlags(&s_join, cudaEventDisableTiming);
    }

    cudaEventRecord(s_fork, 0);
    cudaStreamWaitEvent(s_side, s_fork, 0);

    // ---- main stream ----
    argmin_kernel<<<NB, 32>>>(phi);                       // our launch 0
    {
        dim3 g(NX / 32, NX / 32), blk(32, 32);
        prep_W_bf16<<<g, blk>>>(W);                       // our launch 1
    }
    prep_phi_kernel<<<NB * NT, 128>>>(phi);               // our launch 2
    {
        dim3 grid(NX / BN, NT / BM, NB);
        gemm_tc_kernel<<<grid, 256>>>(out);               // our launch 3 (ncu target)
    }

    // ---- side stream: fp32 logdet chain ----
    copy_Wf<<<(NX * NX + 255) / 256, 256, 0, s_side>>>(W);
    for (int p = 0; p < NX / LU_NB - 1; p++) {
        int k0 = p * LU_NB;
        int nblk = (NX - k0 - LU_NB) / LU_NB;             // 15 .. 1
        dim3 g(nblk, nblk);
        lu_step<<<g, 256, 0, s_side>>>(k0);
    }
    lu_last<<<1, 256, 0, s_side>>>(NX - LU_NB);
    write_logdet_kernel<<<1, NB, 0, s_side>>>(out + (out_size - NB));

    cudaEventRecord(s_join, s_side);
    cudaStreamWaitEvent(0, s_join, 0);
}

// round 13
// speedup vs baseline: 4.4489x; 1.0542x over previous
#include <cuda_runtime.h>
#include <cuda_bf16.h>
#include <math.h>
#include <stdint.h>

#define NB  256
#define NT  512
#define NX  512

// ---------------------------------------------------------------------------
// Device scratch (static; no allocations anywhere)
// ---------------------------------------------------------------------------
__device__ __nv_bfloat16 g_phi_hi[(size_t)NB * NT * NX];  // rolled phi, hi half
__device__ __nv_bfloat16 g_phi_lo[(size_t)NB * NT * NX];  // rolled phi, lo half
__device__ __nv_bfloat16 g_wt_hi[(size_t)NX * NX];        // W^T hi  [y][x]
__device__ __nv_bfloat16 g_wt_lo[(size_t)NX * NX];        // W^T lo  [y][x]
__device__ int    g_T0[NB];
__device__ float  g_Wf[NX * NX];                          // fp32 LU workspace
__device__ double g_logabsdet;

// ---------------------------------------------------------------------------
// PTX helpers (sm_80-era, safe on compute_103)
// ---------------------------------------------------------------------------
__device__ __forceinline__ uint32_t smem_u32(const void* p) {
    uint32_t a;
    asm("{ .reg .u64 t; cvta.to.shared.u64 t, %1; cvt.u32.u64 %0, t; }" : "=r"(a) : "l"(p));
    return a;
}
__device__ __forceinline__ void cp_async16(uint32_t dst, const void* src) {
    asm volatile("cp.async.cg.shared.global [%0], [%1], 16;" :: "r"(dst), "l"(src) : "memory");
}
#define CP_COMMIT() asm volatile("cp.async.commit_group;" ::: "memory")

__device__ __forceinline__ void ldsm_x4(uint32_t* r, uint32_t addr) {
    asm volatile("ldmatrix.sync.aligned.m8n8.x4.shared.b16 {%0,%1,%2,%3}, [%4];"
        : "=r"(r[0]), "=r"(r[1]), "=r"(r[2]), "=r"(r[3]) : "r"(addr));
}
__device__ __forceinline__ void mma16816(float* c, const uint32_t* a, const uint32_t* b) {
    asm volatile("mma.sync.aligned.m16n8k16.row.col.f32.bf16.bf16.f32 "
        "{%0,%1,%2,%3}, {%4,%5,%6,%7}, {%8,%9}, {%0,%1,%2,%3};"
        : "+f"(c[0]), "+f"(c[1]), "+f"(c[2]), "+f"(c[3])
        : "r"(a[0]), "r"(a[1]), "r"(a[2]), "r"(a[3]), "r"(b[0]), "r"(b[1]));
}

// ---------------------------------------------------------------------------
// argmin -> T0 per sample
// ---------------------------------------------------------------------------
__global__ void argmin_kernel(const float* __restrict__ phi) {
    int b = blockIdx.x, lane = threadIdx.x;
    const float* p = phi + (size_t)b * NT * NX;
    float bv0 = 1e38f; int bi0 = 0;
    float bv1 = 1e38f; int bi1 = 0;
    for (int t = lane; t < NT; t += 32) {
        float v0 = fabsf(p[(size_t)t * NX + 0]);
        float v1 = fabsf(p[(size_t)t * NX + 1]);
        if (v0 < bv0) { bv0 = v0; bi0 = t; }
        if (v1 < bv1) { bv1 = v1; bi1 = t; }
    }
    #pragma unroll
    for (int o = 16; o; o >>= 1) {
        float ov = __shfl_down_sync(0xffffffffu, bv0, o);
        int   oi = __shfl_down_sync(0xffffffffu, bi0, o);
        if (ov < bv0 || (ov == bv0 && oi < bi0)) { bv0 = ov; bi0 = oi; }
        ov = __shfl_down_sync(0xffffffffu, bv1, o);
        oi = __shfl_down_sync(0xffffffffu, bi1, o);
        if (ov < bv1 || (ov == bv1 && oi < bi1)) { bv1 = ov; bi1 = oi; }
    }
    if (lane == 0) g_T0[b] = (bi0 > bi1) ? bi1 : bi0;
}

// ---------------------------------------------------------------------------
// W prep (main stream): transpose-split to bf16 hi/lo (GEMM B operand)
// ---------------------------------------------------------------------------
__global__ void prep_W_bf16(const float* __restrict__ W) {
    __shared__ float t[32][33];
    int tx = threadIdx.x, ty = threadIdx.y;
    int r = blockIdx.y * 32 + ty, c = blockIdx.x * 32 + tx;
    t[ty][tx] = W[(size_t)r * NX + c];
    __syncthreads();
    int rr = blockIdx.x * 32 + ty, cc = blockIdx.y * 32 + tx;
    float v = t[tx][ty];
    __nv_bfloat16 hi = __float2bfloat16(v);
    __nv_bfloat16 lo = __float2bfloat16(v - __bfloat162float(hi));
    g_wt_hi[(size_t)rr * NX + cc] = hi;
    g_wt_lo[(size_t)rr * NX + cc] = lo;
}

// ---------------------------------------------------------------------------
// W prep (side stream): fp32 copy + logdet reset
// ---------------------------------------------------------------------------
__global__ void copy_Wf(const float* __restrict__ W) {
    int i = blockIdx.x * blockDim.x + threadIdx.x;
    if (i < NX * NX) g_Wf[i] = W[i];
    if (i == 0) g_logabsdet = 0.0;
}

// ---------------------------------------------------------------------------
// phi prep: roll along x by +T0 and split to bf16 hi/lo.
// ---------------------------------------------------------------------------
__global__ void prep_phi_kernel(const float* __restrict__ phi) {
    int row = blockIdx.x;                 // b*512 + t
    int b = row >> 9;
    int T0 = g_T0[b];
    const float* src = phi + (size_t)row * NX;
    __nv_bfloat16* dh = g_phi_hi + (size_t)row * NX;
    __nv_bfloat16* dl = g_phi_lo + (size_t)row * NX;
    for (int u = threadIdx.x; u < NX; u += 128) {
        float f = src[(u - T0) & (NX - 1)];
        __nv_bfloat16 hi = __float2bfloat16(f);
        __nv_bfloat16 lo = __float2bfloat16(f - __bfloat162float(hi));
        dh[u] = hi; dl[u] = lo;
    }
}

// ---------------------------------------------------------------------------
// Fully distributed fp32 GENP LU step (nb=32). See R12 notes. Smem rows
// padded to 36 floats so float4 accesses at [rr][c4] stay 16B-aligned.
// ---------------------------------------------------------------------------
#define LU_NB 32
#define LPAD  36

__global__ void __launch_bounds__(256) lu_step(int k0) {
    __shared__ float D[32][LPAD];
    __shared__ float U12[32][LPAD];
    __shared__ float L21[32][LPAD];
    __shared__ float s_uinv[32];

    const int tid = threadIdx.x;            // 256
    const int rr  = tid >> 3;               // 0..31
    const int c4  = (tid & 7) * 4;          // 0..28 step 4
    const int r0 = k0 + 32 + blockIdx.y * 32;
    const int c0 = k0 + 32 + blockIdx.x * 32;

    {
        float4 d  = *(const float4*)&g_Wf[(size_t)(k0 + rr) * NX + k0 + c4];
        float4 l  = *(const float4*)&g_Wf[(size_t)(r0 + rr) * NX + k0 + c4];
        float4 u  = *(const float4*)&g_Wf[(size_t)(k0 + rr) * NX + c0 + c4];
        *(float4*)&D[rr][c4]   = d;
        *(float4*)&L21[rr][c4] = l;
        *(float4*)&U12[rr][c4] = u;
    }
    __syncthreads();

    if (tid < 32) {
        const int r = tid;
        #pragma unroll
        for (int j = 0; j < 31; j++) {
            if (r > j) {
                float m = D[r][j] / D[j][j];
                D[r][j] = m;
                #pragma unroll
                for (int c = 0; c < 32; c++)
                    if (c > j) D[r][c] -= m * D[j][c];
            }
            __syncwarp();
        }
        s_uinv[r] = 1.0f / D[r][r];
    }
    __syncthreads();

    if (tid < 32) {
        const int c = tid;
        float u[32];
        #pragma unroll
        for (int i = 0; i < 32; i++) u[i] = U12[i][c];
        #pragma unroll
        for (int i = 0; i < 32; i++) {
            float ui = u[i];
            #pragma unroll
            for (int r = i + 1; r < 32; r++) u[r] -= D[r][i] * ui;
        }
        #pragma unroll
        for (int i = 0; i < 32; i++) U12[i][c] = u[i];
    } else if (tid < 64) {
        const int r = tid - 32;
        float x[32];
        #pragma unroll
        for (int i = 0; i < 32; i++) x[i] = L21[r][i];
        #pragma unroll
        for (int i = 0; i < 32; i++) {
            float xi = x[i] * s_uinv[i];
            x[i] = xi;
            #pragma unroll
            for (int c = i + 1; c < 32; c++) x[c] -= xi * D[i][c];
        }
        #pragma unroll
        for (int i = 0; i < 32; i++) L21[r][i] = x[i];
    }
    __syncthreads();

    float s0 = 0.f, s1 = 0.f, s2 = 0.f, s3 = 0.f;
    #pragma unroll
    for (int k = 0; k < 32; k++) {
        float l = L21[rr][k];
        s0 += l * U12[k][c4 + 0];
        s1 += l * U12[k][c4 + 1];
        s2 += l * U12[k][c4 + 2];
        s3 += l * U12[k][c4 + 3];
    }
    float4* dst = (float4*)&g_Wf[(size_t)(r0 + rr) * NX + c0 + c4];
    float4 old = *dst;
    old.x -= s0; old.y -= s1; old.z -= s2; old.w -= s3;
    *dst = old;

    if (blockIdx.x == 0 && blockIdx.y == 0 && tid < 32) {
        double lg = log(fabs((double)D[tid][tid]));
        #pragma unroll
        for (int o = 16; o; o >>= 1) lg += __shfl_down_sync(0xffffffffu, lg, o);
        if (tid == 0) atomicAdd(&g_logabsdet, lg);
    }
}

// Final 32x32 diagonal block: factor + logs + write logDet outputs.
__global__ void __launch_bounds__(256) lu_last(int k0, float* __restrict__ out_ld) {
    __shared__ float D[32][LPAD];
    const int tid = threadIdx.x;
    const int rr = tid >> 3, c4 = (tid & 7) * 4;
    *(float4*)&D[rr][c4] = *(const float4*)&g_Wf[(size_t)(k0 + rr) * NX + k0 + c4];
    __syncthreads();
    if (tid < 32) {
        const int r = tid;
        #pragma unroll
        for (int j = 0; j < 31; j++) {
            if (r > j) {
                float m = D[r][j] / D[j][j];
                #pragma unroll
                for (int c = 0; c < 32; c++)
                    if (c > j) D[r][c] -= m * D[j][c];
            }
            __syncwarp();
        }
    }
    __syncthreads();
    if (tid < 32) {
        double lg = log(fabs((double)D[tid][tid]));
        #pragma unroll
        for (int o = 16; o; o >>= 1) lg += __shfl_down_sync(0xffffffffu, lg, o);
        if (tid == 0) atomicAdd(&g_logabsdet, lg);
    }
    __syncthreads();
    // broadcast logDet to all NB outputs (g_logabsdet final after the atomic)
    float v = (float)((double)NT * g_logabsdet);
    if (tid < NB) out_ld[tid] = v;
}

// ---------------------------------------------------------------------------
// HMMA bf16 GEMM, K = 3*512 concatenated (hi*hi, hi*lo, lo*hi).
// Tile 128x128, 8 warps, BK=32. 3-stage cp.async pipeline in DYNAMIC smem
// (61.4 KB > 48 KB static limit), ONE __syncthreads per iteration:
// iter it computes stage it%3 while loads fill (it+2)%3; the top barrier
// publishes load(it) and protects stage (it-1)%3 == (it+2)%3 for overwrite.
// ---------------------------------------------------------------------------
#define BM 128
#define BN 128
#define SROW 80                 // bytes per smem row (32 bf16 + 8 pad)
#define STAGE_BYTES (128 * SROW)
#define NSTAGE 3
#define G_SMEM (2 * NSTAGE * STAGE_BYTES)   // 61440
#define NITER 48                // 3 passes * 16 k-chunks of 32

__global__ void __launch_bounds__(256, 2)
gemm_tc_kernel(float* __restrict__ out) {
    extern __shared__ __align__(16) char smem[];

    const int tid  = threadIdx.x;
    const int lane = tid & 31;
    const int wid  = tid >> 5;
    const int wr   = wid >> 2;          // 0..1  (m)
    const int wc   = wid & 3;           // 0..3  (n)

    const int b  = blockIdx.z;
    const int n0 = blockIdx.x * BN;
    const int m0 = blockIdx.y * BM;
    const int T0 = g_T0[b];

    const uint32_t sAu = smem_u32(smem);                        // A stages
    const uint32_t sBu = sAu + NSTAGE * STAGE_BYTES;            // B stages

    const char* aP[3];
    const char* bP[3];
    {
        const char* ph = (const char*)(g_phi_hi + (size_t)b * NT * NX);
        const char* pl = (const char*)(g_phi_lo + (size_t)b * NT * NX);
        aP[0] = ph; aP[1] = ph; aP[2] = pl;
        bP[0] = (const char*)g_wt_hi; bP[1] = (const char*)g_wt_lo; bP[2] = (const char*)g_wt_hi;
    }

    auto load_iter = [&](int it) {
        int p = it >> 4, c = it & 15, s = it % NSTAGE;
        size_t kofs = (size_t)c * 64;
        const char* asrc = aP[p];
        const char* bsrc = bP[p];
        #pragma unroll
        for (int rep = 0; rep < 2; rep++) {
            int idx = tid + rep * 256;          // 0..511
            int row = idx >> 2;
            int q   = idx & 3;
            uint32_t dofs = (uint32_t)(row * SROW + q * 16);
            cp_async16(sAu + s * STAGE_BYTES + dofs,
                       asrc + (size_t)(m0 + row) * 1024 + kofs + q * 16);
            cp_async16(sBu + s * STAGE_BYTES + dofs,
                       bsrc + (size_t)(n0 + row) * 1024 + kofs + q * 16);
        }
        CP_COMMIT();
    };

    float acc[4][4][4];
    #pragma unroll
    for (int i = 0; i < 4; i++)
        #pragma unroll
        for (int j = 0; j < 4; j++)
            #pragma unroll
            for (int q = 0; q < 4; q++) acc[i][j][q] = 0.0f;

    const int lm  = lane & 15;
    const int lk8 = lane >> 4;
    const int bn  = (lane & 7) + ((lane >> 4) << 3);
    const int bk8 = (lane >> 3) & 1;

    const uint32_t aLaneOfs = (uint32_t)((wr * 64 + lm) * SROW + lk8 * 16);
    const uint32_t bLaneOfs = (uint32_t)((wc * 32 + bn) * SROW + bk8 * 16);

    load_iter(0);
    load_iter(1);

    for (int it = 0; it < NITER; it++) {
        int s = it % NSTAGE;
        // publish load(it); keep the newer group(s) in flight
        if (it == NITER - 1) {
            asm volatile("cp.async.wait_group 0;" ::: "memory");
        } else {
            asm volatile("cp.async.wait_group 1;" ::: "memory");
        }
        __syncthreads();    // also guards stage (it+2)%3 == (it-1)%3 reuse

        if (it + 2 < NITER) load_iter(it + 2);

        const uint32_t aStage = sAu + s * STAGE_BYTES + aLaneOfs;
        const uint32_t bStage = sBu + s * STAGE_BYTES + bLaneOfs;

        #pragma unroll
        for (int ks = 0; ks < 2; ks++) {
            uint32_t af[4][4];
            #pragma unroll
            for (int i = 0; i < 4; i++)
                ldsm_x4(af[i], aStage + i * (16 * SROW) + ks * 32);
            uint32_t bf[2][4];
            #pragma unroll
            for (int jp = 0; jp < 2; jp++)
                ldsm_x4(bf[jp], bStage + jp * (16 * SROW) + ks * 32);
            #pragma unroll
            for (int i = 0; i < 4; i++)
                #pragma unroll
                for (int j = 0; j < 4; j++)
                    mma16816(acc[i][j], af[i], &bf[j >> 1][(j & 1) * 2]);
        }
    }

    float* C = out + (size_t)b * NT * NX;
    #pragma unroll
    for (int i = 0; i < 4; i++) {
        int m_lo = m0 + wr * 64 + i * 16 + (lane >> 2);
        int m_hi = m_lo + 8;
        int or_lo = (m_lo - T0 + NT) & (NT - 1);
        int or_hi = (m_hi - T0 + NT) & (NT - 1);
        #pragma unroll
        for (int j = 0; j < 4; j++) {
            int col = n0 + wc * 32 + j * 8 + (lane & 3) * 2;
            *(float2*)(C + (size_t)or_lo * NX + col) = make_float2(acc[i][j][0], acc[i][j][1]);
            *(float2*)(C + (size_t)or_hi * NX + col) = make_float2(acc[i][j][2], acc[i][j][3]);
        }
    }
}

// ---------------------------------------------------------------------------
// Launch. Main stream: argmin(0), prepW(1), prep_phi(2), GEMM(3 <- profiled).
// Side stream (event fork/join): fp32 distributed GENP LU chain + logdet.
// ---------------------------------------------------------------------------
extern "C" void kernel_launch(void* const* d_in, const int* in_sizes, int n_in,
                              void* d_out, int out_size) {
    const float* phi = (const float*)d_in[0];
    const float* W   = (const float*)d_in[1];
    float* out = (float*)d_out;

    static cudaStream_t s_side = nullptr;
    static cudaEvent_t  s_fork = nullptr, s_join = nullptr;
    if (s_side == nullptr) {
        cudaStreamCreateWithFlags(&s_side, cudaStreamNonBlocking);
        cudaEventCreateWithFlags(&s_fork, cudaEventDisableTiming);
        cudaEventCreateWithFlags(&s_join, cudaEventDisableTiming);
        cudaFuncSetAttribute(gemm_tc_kernel,
                             cudaFuncAttributeMaxDynamicSharedMemorySize, G_SMEM);
    }

    cudaEventRecord(s_fork, 0);
    cudaStreamWaitEvent(s_side, s_fork, 0);

    // ---- main stream ----
    argmin_kernel<<<NB, 32>>>(phi);                       // our launch 0
    {
        dim3 g(NX / 32, NX / 32), blk(32, 32);
        prep_W_bf16<<<g, blk>>>(W);                       // our launch 1
    }
    prep_phi_kernel<<<NB * NT, 128>>>(phi);               // our launch 2
    {
        dim3 grid(NX / BN, NT / BM, NB);
        gemm_tc_kernel<<<grid, 256, G_SMEM>>>(out);       // our launch 3 (ncu target)
    }

    // ---- side stream: fp32 logdet chain ----
    copy_Wf<<<(NX * NX + 255) / 256, 256, 0, s_side>>>(W);
    for (int p = 0; p < NX / LU_NB - 1; p++) {
        int k0 = p * LU_NB;
        int nblk = (NX - k0 - LU_NB) / LU_NB;             // 15 .. 1
        dim3 g(nblk, nblk);
        lu_step<<<g, 256, 0, s_side>>>(k0);
    }
    lu_last<<<1, 256, 0, s_side>>>(NX - LU_NB, out + (out_size - NB));

    cudaEventRecord(s_join, s_side);
    cudaStreamWaitEvent(0, s_join, 0);
}

// round 14
// speedup vs baseline: 4.6515x; 1.0455x over previous
#include <cuda_runtime.h>
#include <cuda_bf16.h>
#include <math.h>
#include <stdint.h>

#define NB  256
#define NT  512
#define NX  512

// ---------------------------------------------------------------------------
// Device scratch (static; no allocations anywhere)
// ---------------------------------------------------------------------------
__device__ __nv_bfloat16 g_phi_hi[(size_t)NB * NT * NX];  // rolled phi, hi half
__device__ __nv_bfloat16 g_phi_lo[(size_t)NB * NT * NX];  // rolled phi, lo half
__device__ __nv_bfloat16 g_wt_hi[(size_t)NX * NX];        // W^T hi  [y][x]
__device__ __nv_bfloat16 g_wt_lo[(size_t)NX * NX];        // W^T lo  [y][x]
__device__ int    g_T0[NB];
__device__ float  g_Wf[NX * NX];                          // fp32 LU workspace
__device__ double g_logabsdet;

// ---------------------------------------------------------------------------
// PTX helpers (sm_80-era, safe on compute_103)
// ---------------------------------------------------------------------------
__device__ __forceinline__ uint32_t smem_u32(const void* p) {
    uint32_t a;
    asm("{ .reg .u64 t; cvta.to.shared.u64 t, %1; cvt.u32.u64 %0, t; }" : "=r"(a) : "l"(p));
    return a;
}
__device__ __forceinline__ void cp_async16(uint32_t dst, const void* src) {
    asm volatile("cp.async.cg.shared.global [%0], [%1], 16;" :: "r"(dst), "l"(src) : "memory");
}
#define CP_COMMIT() asm volatile("cp.async.commit_group;" ::: "memory")

__device__ __forceinline__ void ldsm_x4(uint32_t* r, uint32_t addr) {
    asm volatile("ldmatrix.sync.aligned.m8n8.x4.shared.b16 {%0,%1,%2,%3}, [%4];"
        : "=r"(r[0]), "=r"(r[1]), "=r"(r[2]), "=r"(r[3]) : "r"(addr));
}
__device__ __forceinline__ void mma16816(float* c, const uint32_t* a, const uint32_t* b) {
    asm volatile("mma.sync.aligned.m16n8k16.row.col.f32.bf16.bf16.f32 "
        "{%0,%1,%2,%3}, {%4,%5,%6,%7}, {%8,%9}, {%0,%1,%2,%3};"
        : "+f"(c[0]), "+f"(c[1]), "+f"(c[2]), "+f"(c[3])
        : "r"(a[0]), "r"(a[1]), "r"(a[2]), "r"(a[3]), "r"(b[0]), "r"(b[1]));
}

// ---------------------------------------------------------------------------
// argmin -> T0 per sample
// ---------------------------------------------------------------------------
__global__ void argmin_kernel(const float* __restrict__ phi) {
    int b = blockIdx.x, lane = threadIdx.x;
    const float* p = phi + (size_t)b * NT * NX;
    float bv0 = 1e38f; int bi0 = 0;
    float bv1 = 1e38f; int bi1 = 0;
    for (int t = lane; t < NT; t += 32) {
        float v0 = fabsf(p[(size_t)t * NX + 0]);
        float v1 = fabsf(p[(size_t)t * NX + 1]);
        if (v0 < bv0) { bv0 = v0; bi0 = t; }
        if (v1 < bv1) { bv1 = v1; bi1 = t; }
    }
    #pragma unroll
    for (int o = 16; o; o >>= 1) {
        float ov = __shfl_down_sync(0xffffffffu, bv0, o);
        int   oi = __shfl_down_sync(0xffffffffu, bi0, o);
        if (ov < bv0 || (ov == bv0 && oi < bi0)) { bv0 = ov; bi0 = oi; }
        ov = __shfl_down_sync(0xffffffffu, bv1, o);
        oi = __shfl_down_sync(0xffffffffu, bi1, o);
        if (ov < bv1 || (ov == bv1 && oi < bi1)) { bv1 = ov; bi1 = oi; }
    }
    if (lane == 0) g_T0[b] = (bi0 > bi1) ? bi1 : bi0;
}

// ---------------------------------------------------------------------------
// W prep (main stream): transpose-split to bf16 hi/lo (GEMM B operand)
// ---------------------------------------------------------------------------
__global__ void prep_W_bf16(const float* __restrict__ W) {
    __shared__ float t[32][33];
    int tx = threadIdx.x, ty = threadIdx.y;
    int r = blockIdx.y * 32 + ty, c = blockIdx.x * 32 + tx;
    t[ty][tx] = W[(size_t)r * NX + c];
    __syncthreads();
    int rr = blockIdx.x * 32 + ty, cc = blockIdx.y * 32 + tx;
    float v = t[tx][ty];
    __nv_bfloat16 hi = __float2bfloat16(v);
    __nv_bfloat16 lo = __float2bfloat16(v - __bfloat162float(hi));
    g_wt_hi[(size_t)rr * NX + cc] = hi;
    g_wt_lo[(size_t)rr * NX + cc] = lo;
}

// ---------------------------------------------------------------------------
// W prep (side stream): fp32 copy + logdet reset
// ---------------------------------------------------------------------------
__global__ void copy_Wf(const float* __restrict__ W) {
    int i = blockIdx.x * blockDim.x + threadIdx.x;
    if (i < NX * NX) g_Wf[i] = W[i];
    if (i == 0) g_logabsdet = 0.0;
}

// ---------------------------------------------------------------------------
// phi prep: roll along x by +T0 and split to bf16 hi/lo.
// ---------------------------------------------------------------------------
__global__ void prep_phi_kernel(const float* __restrict__ phi) {
    int row = blockIdx.x;                 // b*512 + t
    int b = row >> 9;
    int T0 = g_T0[b];
    const float* src = phi + (size_t)row * NX;
    __nv_bfloat16* dh = g_phi_hi + (size_t)row * NX;
    __nv_bfloat16* dl = g_phi_lo + (size_t)row * NX;
    for (int u = threadIdx.x; u < NX; u += 128) {
        float f = src[(u - T0) & (NX - 1)];
        __nv_bfloat16 hi = __float2bfloat16(f);
        __nv_bfloat16 lo = __float2bfloat16(f - __bfloat162float(hi));
        dh[u] = hi; dl[u] = lo;
    }
}

// ---------------------------------------------------------------------------
// Fully distributed fp32 GENP LU step (nb=32). Smem rows padded to 36 floats
// so float4 accesses at [rr][c4] stay 16B-aligned.
// ---------------------------------------------------------------------------
#define LU_NB 32
#define LPAD  36

__global__ void __launch_bounds__(256) lu_step(int k0) {
    __shared__ float D[32][LPAD];
    __shared__ float U12[32][LPAD];
    __shared__ float L21[32][LPAD];
    __shared__ float s_uinv[32];

    const int tid = threadIdx.x;            // 256
    const int rr  = tid >> 3;               // 0..31
    const int c4  = (tid & 7) * 4;          // 0..28 step 4
    const int r0 = k0 + 32 + blockIdx.y * 32;
    const int c0 = k0 + 32 + blockIdx.x * 32;

    {
        float4 d  = *(const float4*)&g_Wf[(size_t)(k0 + rr) * NX + k0 + c4];
        float4 l  = *(const float4*)&g_Wf[(size_t)(r0 + rr) * NX + k0 + c4];
        float4 u  = *(const float4*)&g_Wf[(size_t)(k0 + rr) * NX + c0 + c4];
        *(float4*)&D[rr][c4]   = d;
        *(float4*)&L21[rr][c4] = l;
        *(float4*)&U12[rr][c4] = u;
    }
    __syncthreads();

    if (tid < 32) {
        const int r = tid;
        #pragma unroll
        for (int j = 0; j < 31; j++) {
            if (r > j) {
                float m = D[r][j] / D[j][j];
                D[r][j] = m;
                #pragma unroll
                for (int c = 0; c < 32; c++)
                    if (c > j) D[r][c] -= m * D[j][c];
            }
            __syncwarp();
        }
        s_uinv[r] = 1.0f / D[r][r];
    }
    __syncthreads();

    if (tid < 32) {
        const int c = tid;
        float u[32];
        #pragma unroll
        for (int i = 0; i < 32; i++) u[i] = U12[i][c];
        #pragma unroll
        for (int i = 0; i < 32; i++) {
            float ui = u[i];
            #pragma unroll
            for (int r = i + 1; r < 32; r++) u[r] -= D[r][i] * ui;
        }
        #pragma unroll
        for (int i = 0; i < 32; i++) U12[i][c] = u[i];
    } else if (tid < 64) {
        const int r = tid - 32;
        float x[32];
        #pragma unroll
        for (int i = 0; i < 32; i++) x[i] = L21[r][i];
        #pragma unroll
        for (int i = 0; i < 32; i++) {
            float xi = x[i] * s_uinv[i];
            x[i] = xi;
            #pragma unroll
            for (int c = i + 1; c < 32; c++) x[c] -= xi * D[i][c];
        }
        #pragma unroll
        for (int i = 0; i < 32; i++) L21[r][i] = x[i];
    }
    __syncthreads();

    float s0 = 0.f, s1 = 0.f, s2 = 0.f, s3 = 0.f;
    #pragma unroll
    for (int k = 0; k < 32; k++) {
        float l = L21[rr][k];
        s0 += l * U12[k][c4 + 0];
        s1 += l * U12[k][c4 + 1];
        s2 += l * U12[k][c4 + 2];
        s3 += l * U12[k][c4 + 3];
    }
    float4* dst = (float4*)&g_Wf[(size_t)(r0 + rr) * NX + c0 + c4];
    float4 old = *dst;
    old.x -= s0; old.y -= s1; old.z -= s2; old.w -= s3;
    *dst = old;

    if (blockIdx.x == 0 && blockIdx.y == 0 && tid < 32) {
        double lg = log(fabs((double)D[tid][tid]));
        #pragma unroll
        for (int o = 16; o; o >>= 1) lg += __shfl_down_sync(0xffffffffu, lg, o);
        if (tid == 0) atomicAdd(&g_logabsdet, lg);
    }
}

// Final 32x32 diagonal block: factor + logs + write logDet outputs.
__global__ void __launch_bounds__(256) lu_last(int k0, float* __restrict__ out_ld) {
    __shared__ float D[32][LPAD];
    const int tid = threadIdx.x;
    const int rr = tid >> 3, c4 = (tid & 7) * 4;
    *(float4*)&D[rr][c4] = *(const float4*)&g_Wf[(size_t)(k0 + rr) * NX + k0 + c4];
    __syncthreads();
    if (tid < 32) {
        const int r = tid;
        #pragma unroll
        for (int j = 0; j < 31; j++) {
            if (r > j) {
                float m = D[r][j] / D[j][j];
                #pragma unroll
                for (int c = 0; c < 32; c++)
                    if (c > j) D[r][c] -= m * D[j][c];
            }
            __syncwarp();
        }
    }
    __syncthreads();
    if (tid < 32) {
        double lg = log(fabs((double)D[tid][tid]));
        #pragma unroll
        for (int o = 16; o; o >>= 1) lg += __shfl_down_sync(0xffffffffu, lg, o);
        if (tid == 0) atomicAdd(&g_logabsdet, lg);
    }
    __syncthreads();
    float v = (float)((double)NT * g_logabsdet);
    if (tid < NB) out_ld[tid] = v;
}

// ---------------------------------------------------------------------------
// HMMA bf16 GEMM, K = 3*512 concatenated (hi*hi, hi*lo, lo*hi).
// Tile 128x128, 8 warps, BK=64 (128B slab / iter, 4 mma k-steps), 24 iters.
// 3-stage cp.async pipeline in dynamic smem (110.6 KB; 2 CTAs/SM), ONE
// __syncthreads per iteration (same distance-2 pattern as R13).
// ---------------------------------------------------------------------------
#define BM 128
#define BN 128
#define SROW 144                 // bytes per smem row (64 bf16 + 16B pad)
#define STAGE_BYTES (128 * SROW) // 18432 per operand
#define NSTAGE 3
#define G_SMEM (2 * NSTAGE * STAGE_BYTES)   // 110592
#define NITER 24                 // 3 passes * 8 k-chunks of 64

__global__ void __launch_bounds__(256, 2)
gemm_tc_kernel(float* __restrict__ out) {
    extern __shared__ __align__(16) char smem[];

    const int tid  = threadIdx.x;
    const int lane = tid & 31;
    const int wid  = tid >> 5;
    const int wr   = wid >> 2;          // 0..1  (m)
    const int wc   = wid & 3;           // 0..3  (n)

    const int b  = blockIdx.z;
    const int n0 = blockIdx.x * BN;
    const int m0 = blockIdx.y * BM;
    const int T0 = g_T0[b];

    const uint32_t sAu = smem_u32(smem);
    const uint32_t sBu = sAu + NSTAGE * STAGE_BYTES;

    const char* aP[3];
    const char* bP[3];
    {
        const char* ph = (const char*)(g_phi_hi + (size_t)b * NT * NX);
        const char* pl = (const char*)(g_phi_lo + (size_t)b * NT * NX);
        aP[0] = ph; aP[1] = ph; aP[2] = pl;
        bP[0] = (const char*)g_wt_hi; bP[1] = (const char*)g_wt_lo; bP[2] = (const char*)g_wt_hi;
    }

    // loader: 128 rows x 128B per operand; 256 threads x 4 x16B per operand
    auto load_iter = [&](int it) {
        int p = it >> 3, c = it & 7, s = it % NSTAGE;
        size_t kofs = (size_t)c * 128;
        const char* asrc = aP[p];
        const char* bsrc = bP[p];
        #pragma unroll
        for (int rep = 0; rep < 4; rep++) {
            int idx = tid + rep * 256;          // 0..1023
            int row = idx >> 3;
            int q   = idx & 7;
            uint32_t dofs = (uint32_t)(row * SROW + q * 16);
            cp_async16(sAu + s * STAGE_BYTES + dofs,
                       asrc + (size_t)(m0 + row) * 1024 + kofs + q * 16);
            cp_async16(sBu + s * STAGE_BYTES + dofs,
                       bsrc + (size_t)(n0 + row) * 1024 + kofs + q * 16);
        }
        CP_COMMIT();
    };

    float acc[4][4][4];
    #pragma unroll
    for (int i = 0; i < 4; i++)
        #pragma unroll
        for (int j = 0; j < 4; j++)
            #pragma unroll
            for (int q = 0; q < 4; q++) acc[i][j][q] = 0.0f;

    const int lm  = lane & 15;
    const int lk8 = lane >> 4;
    const int bn  = (lane & 7) + ((lane >> 4) << 3);
    const int bk8 = (lane >> 3) & 1;

    const uint32_t aLaneOfs = (uint32_t)((wr * 64 + lm) * SROW + lk8 * 16);
    const uint32_t bLaneOfs = (uint32_t)((wc * 32 + bn) * SROW + bk8 * 16);

    load_iter(0);
    load_iter(1);

    for (int it = 0; it < NITER; it++) {
        int s = it % NSTAGE;
        if (it == NITER - 1) {
            asm volatile("cp.async.wait_group 0;" ::: "memory");
        } else {
            asm volatile("cp.async.wait_group 1;" ::: "memory");
        }
        __syncthreads();    // publishes load(it); guards stage (it+2)%3 reuse

        if (it + 2 < NITER) load_iter(it + 2);

        const uint32_t aStage = sAu + s * STAGE_BYTES + aLaneOfs;
        const uint32_t bStage = sBu + s * STAGE_BYTES + bLaneOfs;

        #pragma unroll
        for (int ks = 0; ks < 4; ks++) {    // four k16 steps in BK=64
            uint32_t af[4][4];
            #pragma unroll
            for (int i = 0; i < 4; i++)
                ldsm_x4(af[i], aStage + i * (16 * SROW) + ks * 32);
            uint32_t bf[2][4];
            #pragma unroll
            for (int jp = 0; jp < 2; jp++)
                ldsm_x4(bf[jp], bStage + jp * (16 * SROW) + ks * 32);
            #pragma unroll
            for (int i = 0; i < 4; i++)
                #pragma unroll
                for (int j = 0; j < 4; j++)
                    mma16816(acc[i][j], af[i], &bf[j >> 1][(j & 1) * 2]);
        }
    }

    float* C = out + (size_t)b * NT * NX;
    #pragma unroll
    for (int i = 0; i < 4; i++) {
        int m_lo = m0 + wr * 64 + i * 16 + (lane >> 2);
        int m_hi = m_lo + 8;
        int or_lo = (m_lo - T0 + NT) & (NT - 1);
        int or_hi = (m_hi - T0 + NT) & (NT - 1);
        #pragma unroll
        for (int j = 0; j < 4; j++) {
            int col = n0 + wc * 32 + j * 8 + (lane & 3) * 2;
            *(float2*)(C + (size_t)or_lo * NX + col) = make_float2(acc[i][j][0], acc[i][j][1]);
            *(float2*)(C + (size_t)or_hi * NX + col) = make_float2(acc[i][j][2], acc[i][j][3]);
        }
    }
}

// ---------------------------------------------------------------------------
// Launch. Main stream: argmin(0), prepW(1), prep_phi(2), GEMM(3 <- profiled).
// Side stream (event fork/join): fp32 distributed GENP LU chain + logdet.
// ---------------------------------------------------------------------------
extern "C" void kernel_launch(void* const* d_in, const int* in_sizes, int n_in,
                              void* d_out, int out_size) {
    const float* phi = (const float*)d_in[0];
    const float* W   = (const float*)d_in[1];
    float* out = (float*)d_out;

    static cudaStream_t s_side = nullptr;
    static cudaEvent_t  s_fork = nullptr, s_join = nullptr;
    if (s_side == nullptr) {
        cudaStreamCreateWithFlags(&s_side, cudaStreamNonBlocking);
        cudaEventCreateWithFlags(&s_fork, cudaEventDisableTiming);
        cudaEventCreateWithFlags(&s_join, cudaEventDisableTiming);
        cudaFuncSetAttribute(gemm_tc_kernel,
                             cudaFuncAttributeMaxDynamicSharedMemorySize, G_SMEM);
    }

    cudaEventRecord(s_fork, 0);
    cudaStreamWaitEvent(s_side, s_fork, 0);

    // ---- main stream ----
    argmin_kernel<<<NB, 32>>>(phi);                       // our launch 0
    {
        dim3 g(NX / 32, NX / 32), blk(32, 32);
        prep_W_bf16<<<g, blk>>>(W);                       // our launch 1
    }
    prep_phi_kernel<<<NB * NT, 128>>>(phi);               // our launch 2
    {
        dim3 grid(NX / BN, NT / BM, NB);
        gemm_tc_kernel<<<grid, 256, G_SMEM>>>(out);       // our launch 3 (ncu target)
    }

    // ---- side stream: fp32 logdet chain ----
    copy_Wf<<<(NX * NX + 255) / 256, 256, 0, s_side>>>(W);
    for (int p = 0; p < NX / LU_NB - 1; p++) {
        int k0 = p * LU_NB;
        int nblk = (NX - k0 - LU_NB) / LU_NB;             // 15 .. 1
        dim3 g(nblk, nblk);
        lu_step<<<g, 256, 0, s_side>>>(k0);
    }
    lu_last<<<1, 256, 0, s_side>>>(NX - LU_NB, out + (out_size - NB));

    cudaEventRecord(s_join, s_side);
    cudaStreamWaitEvent(0, s_join, 0);
}

// round 15
// speedup vs baseline: 5.9412x; 1.2773x over previous
#include <cuda_runtime.h>
#include <cuda_bf16.h>
#include <math.h>
#include <stdint.h>

#define NB  256
#define NT  512
#define NX  512

// ---------------------------------------------------------------------------
// Device scratch (static; no allocations anywhere)
// ---------------------------------------------------------------------------
__device__ __nv_bfloat16 g_phi_hi[(size_t)NB * NT * NX];  // rolled phi, hi half
__device__ __nv_bfloat16 g_phi_lo[(size_t)NB * NT * NX];  // rolled phi, lo half
__device__ __nv_bfloat16 g_wt_hi[(size_t)NX * NX];        // W^T hi  [y][x]
__device__ __nv_bfloat16 g_wt_lo[(size_t)NX * NX];        // W^T lo  [y][x]
__device__ int      g_T0[NB];
__device__ float    g_Wf[NX * NX];                        // fp32 LU workspace
__device__ unsigned g_bar;                                // grid barrier counter

// ---------------------------------------------------------------------------
// PTX helpers (sm_80-era, safe on compute_103)
// ---------------------------------------------------------------------------
__device__ __forceinline__ uint32_t smem_u32(const void* p) {
    uint32_t a;
    asm("{ .reg .u64 t; cvta.to.shared.u64 t, %1; cvt.u32.u64 %0, t; }" : "=r"(a) : "l"(p));
    return a;
}
__device__ __forceinline__ void cp_async16(uint32_t dst, const void* src) {
    asm volatile("cp.async.cg.shared.global [%0], [%1], 16;" :: "r"(dst), "l"(src) : "memory");
}
#define CP_COMMIT() asm volatile("cp.async.commit_group;" ::: "memory")

__device__ __forceinline__ void ldsm_x4(uint32_t* r, uint32_t addr) {
    asm volatile("ldmatrix.sync.aligned.m8n8.x4.shared.b16 {%0,%1,%2,%3}, [%4];"
        : "=r"(r[0]), "=r"(r[1]), "=r"(r[2]), "=r"(r[3]) : "r"(addr));
}
__device__ __forceinline__ void mma16816(float* c, const uint32_t* a, const uint32_t* b) {
    asm volatile("mma.sync.aligned.m16n8k16.row.col.f32.bf16.bf16.f32 "
        "{%0,%1,%2,%3}, {%4,%5,%6,%7}, {%8,%9}, {%0,%1,%2,%3};"
        : "+f"(c[0]), "+f"(c[1]), "+f"(c[2]), "+f"(c[3])
        : "r"(a[0]), "r"(a[1]), "r"(a[2]), "r"(a[3]), "r"(b[0]), "r"(b[1]));
}

// ---------------------------------------------------------------------------
// argmin -> T0 per sample
// ---------------------------------------------------------------------------
__global__ void argmin_kernel(const float* __restrict__ phi) {
    int b = blockIdx.x, lane = threadIdx.x;
    const float* p = phi + (size_t)b * NT * NX;
    float bv0 = 1e38f; int bi0 = 0;
    float bv1 = 1e38f; int bi1 = 0;
    for (int t = lane; t < NT; t += 32) {
        float v0 = fabsf(p[(size_t)t * NX + 0]);
        float v1 = fabsf(p[(size_t)t * NX + 1]);
        if (v0 < bv0) { bv0 = v0; bi0 = t; }
        if (v1 < bv1) { bv1 = v1; bi1 = t; }
    }
    #pragma unroll
    for (int o = 16; o; o >>= 1) {
        float ov = __shfl_down_sync(0xffffffffu, bv0, o);
        int   oi = __shfl_down_sync(0xffffffffu, bi0, o);
        if (ov < bv0 || (ov == bv0 && oi < bi0)) { bv0 = ov; bi0 = oi; }
        ov = __shfl_down_sync(0xffffffffu, bv1, o);
        oi = __shfl_down_sync(0xffffffffu, bi1, o);
        if (ov < bv1 || (ov == bv1 && oi < bi1)) { bv1 = ov; bi1 = oi; }
    }
    if (lane == 0) g_T0[b] = (bi0 > bi1) ? bi1 : bi0;
}

// ---------------------------------------------------------------------------
// W prep (main stream): transpose-split to bf16 hi/lo (GEMM B operand)
// ---------------------------------------------------------------------------
__global__ void prep_W_bf16(const float* __restrict__ W) {
    __shared__ float t[32][33];
    int tx = threadIdx.x, ty = threadIdx.y;
    int r = blockIdx.y * 32 + ty, c = blockIdx.x * 32 + tx;
    t[ty][tx] = W[(size_t)r * NX + c];
    __syncthreads();
    int rr = blockIdx.x * 32 + ty, cc = blockIdx.y * 32 + tx;
    float v = t[tx][ty];
    __nv_bfloat16 hi = __float2bfloat16(v);
    __nv_bfloat16 lo = __float2bfloat16(v - __bfloat162float(hi));
    g_wt_hi[(size_t)rr * NX + cc] = hi;
    g_wt_lo[(size_t)rr * NX + cc] = lo;
}

// ---------------------------------------------------------------------------
// W prep (side stream): fp32 copy + barrier reset
// ---------------------------------------------------------------------------
__global__ void copy_Wf(const float* __restrict__ W) {
    int i = blockIdx.x * blockDim.x + threadIdx.x;
    if (i < NX * NX) g_Wf[i] = W[i];
    if (i == 0) g_bar = 0u;
}

// ---------------------------------------------------------------------------
// phi prep: roll along x by +T0 and split to bf16 hi/lo.
// ---------------------------------------------------------------------------
__global__ void prep_phi_kernel(const float* __restrict__ phi) {
    int row = blockIdx.x;                 // b*512 + t
    int b = row >> 9;
    int T0 = g_T0[b];
    const float* src = phi + (size_t)row * NX;
    __nv_bfloat16* dh = g_phi_hi + (size_t)row * NX;
    __nv_bfloat16* dl = g_phi_lo + (size_t)row * NX;
    for (int u = threadIdx.x; u < NX; u += 128) {
        float f = src[(u - T0) & (NX - 1)];
        __nv_bfloat16 hi = __float2bfloat16(f);
        __nv_bfloat16 lo = __float2bfloat16(f - __bfloat162float(hi));
        dh[u] = hi; dl[u] = lo;
    }
}

// ---------------------------------------------------------------------------
// Single-kernel fp32 GENP LU (logdet only). 8 blocks x 512 threads, grid-wide
// spin barrier (monotonic count, reset by copy_Wf). Per nb=32 step:
//   1a. every block redundantly factors the 32x32 diagonal D in smem (warp 0)
//   1b. 2m panel units (m U12 col-blocks + m L21 row-blocks) distributed
//       one-per-warp across all 128 warps, solved in place in gmem
//   --- grid barrier ---
//   2.  m*m trailing 32x32 tiles updated by 16 concurrent 256-thread groups
//   --- grid barrier ---
// Block 0 accumulates pivot logs in a register; writes all NB outputs at end.
// Spin blocks never obstruct others' progress -> no deadlock even if launched
// while the GEMM saturates the register file.
// ---------------------------------------------------------------------------
#define LUB 8
#define LU_SMEM ((32 * 33 + 32 + 16 * 32 * 36) * 4)   // 78080 bytes

__device__ __forceinline__ void grid_sync(unsigned* barnum, int tid) {
    __syncthreads();
    if (tid == 0) {
        unsigned target = (++(*barnum)) * LUB;
        __threadfence();
        atomicAdd(&g_bar, 1u);
        while (*((volatile unsigned*)&g_bar) < target) { }
        __threadfence();
    }
    __syncthreads();
}

__global__ void __launch_bounds__(512) lu_all(float* __restrict__ out_ld) {
    extern __shared__ float sm[];
    float (*sD)[33] = (float(*)[33])sm;                 // 32x33
    float* uinv    = sm + 32 * 33;                      // 32
    float* bufbase = sm + 32 * 33 + 32;                 // 16 bufs of 32x36

    const int tid  = threadIdx.x;
    const int bid  = blockIdx.x;
    const int wid  = tid >> 5;
    const int lane = tid & 31;
    unsigned barnum = 0;
    double logsum = 0.0;

    for (int s = 0; s < 15; s++) {
        const int k0 = s * 32;
        const int m  = 15 - s;

        // --- 1a: local D factor (warp 0 of every block) ---
        if (wid == 0) {
            for (int r = 0; r < 32; r++)
                sD[r][lane] = g_Wf[(size_t)(k0 + r) * NX + k0 + lane];
            __syncwarp();
            for (int j = 0; j < 31; j++) {
                if (lane > j) {
                    float mf = sD[lane][j] / sD[j][j];
                    sD[lane][j] = mf;
                    for (int c = j + 1; c < 32; c++) sD[lane][c] -= mf * sD[j][c];
                }
                __syncwarp();
            }
            uinv[lane] = 1.0f / sD[lane][lane];
            if (bid == 0) {
                double lg = log(fabs((double)sD[lane][lane]));
                #pragma unroll
                for (int o = 16; o; o >>= 1) lg += __shfl_down_sync(0xffffffffu, lg, o);
                if (lane == 0) logsum += lg;
            }
        }
        __syncthreads();

        // --- 1b: panel solves, one unit per warp ---
        for (int u = bid * 16 + wid; u < 2 * m; u += 128) {
            if (u < m) {
                // U12 col-block: forward-sub with unit-lower L11; lane = column
                int col = k0 + 32 + u * 32 + lane;
                float v[32];
                #pragma unroll
                for (int i = 0; i < 32; i++) v[i] = g_Wf[(size_t)(k0 + i) * NX + col];
                #pragma unroll
                for (int i = 0; i < 32; i++) {
                    float vi = v[i];
                    #pragma unroll
                    for (int r = i + 1; r < 32; r++) v[r] -= sD[r][i] * vi;
                }
                #pragma unroll
                for (int i = 0; i < 32; i++) g_Wf[(size_t)(k0 + i) * NX + col] = v[i];
            } else {
                // L21 row-block: x * U11 = a; staged via smem for coalescing
                int r0 = k0 + 32 + (u - m) * 32;
                float* buf = bufbase + wid * (32 * 36);
                for (int r = 0; r < 32; r++)
                    buf[r * 36 + lane] = g_Wf[(size_t)(r0 + r) * NX + k0 + lane];
                __syncwarp();
                float x[32];
                #pragma unroll
                for (int i = 0; i < 32; i++) x[i] = buf[lane * 36 + i];
                #pragma unroll
                for (int i = 0; i < 32; i++) {
                    float xi = x[i] * uinv[i];
                    x[i] = xi;
                    #pragma unroll
                    for (int c = i + 1; c < 32; c++) x[c] -= xi * sD[i][c];
                }
                #pragma unroll
                for (int i = 0; i < 32; i++) buf[lane * 36 + i] = x[i];
                __syncwarp();
                for (int r = 0; r < 32; r++)
                    g_Wf[(size_t)(r0 + r) * NX + k0 + lane] = buf[r * 36 + lane];
            }
        }
        grid_sync(&barnum, tid);

        // --- 2: trailing tiles, 2 groups of 256 threads per block ---
        const int grp = tid >> 8;
        const int gt  = tid & 255;
        const int ntile = m * m;
        float* L = bufbase + (grp * 2 + 0) * (32 * 36);
        float* U = bufbase + (grp * 2 + 1) * (32 * 36);
        const int nrounds = (ntile + 15) / 16;
        for (int rd = 0; rd < nrounds; rd++) {
            int t = bid * 2 + grp + rd * 16;
            bool act = (t < ntile);
            int r0 = 0, c0 = 0;
            if (act) {
                int ti = t / m, tj = t % m;
                r0 = k0 + 32 + ti * 32;
                c0 = k0 + 32 + tj * 32;
                int row = gt >> 3, c4 = (gt & 7) * 4;
                *(float4*)&L[row * 36 + c4] =
                    *(const float4*)&g_Wf[(size_t)(r0 + row) * NX + k0 + c4];
                *(float4*)&U[row * 36 + c4] =
                    *(const float4*)&g_Wf[(size_t)(k0 + row) * NX + c0 + c4];
            }
            __syncthreads();
            if (act) {
                int r = gt >> 3, c = (gt & 7) * 4;
                float a0 = 0, a1 = 0, a2 = 0, a3 = 0;
                #pragma unroll
                for (int k = 0; k < 32; k++) {
                    float l = L[r * 36 + k];
                    a0 += l * U[k * 36 + c + 0];
                    a1 += l * U[k * 36 + c + 1];
                    a2 += l * U[k * 36 + c + 2];
                    a3 += l * U[k * 36 + c + 3];
                }
                float4* dst = (float4*)&g_Wf[(size_t)(r0 + r) * NX + c0 + c];
                float4 o = *dst;
                o.x -= a0; o.y -= a1; o.z -= a2; o.w -= a3;
                *dst = o;
            }
            __syncthreads();
        }
        grid_sync(&barnum, tid);
    }

    // final 32x32 diagonal (k0=480): logs only, block 0
    if (bid == 0) {
        if (wid == 0) {
            const int k0 = 480;
            for (int r = 0; r < 32; r++)
                sD[r][lane] = g_Wf[(size_t)(k0 + r) * NX + k0 + lane];
            __syncwarp();
            for (int j = 0; j < 31; j++) {
                if (lane > j) {
                    float mf = sD[lane][j] / sD[j][j];
                    for (int c = j + 1; c < 32; c++) sD[lane][c] -= mf * sD[j][c];
                }
                __syncwarp();
            }
            double lg = log(fabs((double)sD[lane][lane]));
            #pragma unroll
            for (int o = 16; o; o >>= 1) lg += __shfl_down_sync(0xffffffffu, lg, o);
            if (lane == 0) uinv[0] = (float)((double)NT * (logsum + lg));
        }
        __syncthreads();
        float v = uinv[0];
        if (tid < NB) out_ld[tid] = v;
    }
}

// ---------------------------------------------------------------------------
// HMMA bf16 GEMM, K = 3*512 concatenated (hi*hi, hi*lo, lo*hi).
// Tile 128x128, 8 warps, BK=64, 3-stage cp.async pipeline (dynamic smem),
// one __syncthreads per iteration, fused output roll. (Unchanged from R14.)
// ---------------------------------------------------------------------------
#define BM 128
#define BN 128
#define SROW 144                 // bytes per smem row (64 bf16 + 16B pad)
#define STAGE_BYTES (128 * SROW)
#define NSTAGE 3
#define G_SMEM (2 * NSTAGE * STAGE_BYTES)   // 110592
#define NITER 24                 // 3 passes * 8 k-chunks of 64

__global__ void __launch_bounds__(256, 2)
gemm_tc_kernel(float* __restrict__ out) {
    extern __shared__ __align__(16) char smem[];

    const int tid  = threadIdx.x;
    const int lane = tid & 31;
    const int wid  = tid >> 5;
    const int wr   = wid >> 2;
    const int wc   = wid & 3;

    const int b  = blockIdx.z;
    const int n0 = blockIdx.x * BN;
    const int m0 = blockIdx.y * BM;
    const int T0 = g_T0[b];

    const uint32_t sAu = smem_u32(smem);
    const uint32_t sBu = sAu + NSTAGE * STAGE_BYTES;

    const char* aP[3];
    const char* bP[3];
    {
        const char* ph = (const char*)(g_phi_hi + (size_t)b * NT * NX);
        const char* pl = (const char*)(g_phi_lo + (size_t)b * NT * NX);
        aP[0] = ph; aP[1] = ph; aP[2] = pl;
        bP[0] = (const char*)g_wt_hi; bP[1] = (const char*)g_wt_lo; bP[2] = (const char*)g_wt_hi;
    }

    auto load_iter = [&](int it) {
        int p = it >> 3, c = it & 7, s = it % NSTAGE;
        size_t kofs = (size_t)c * 128;
        const char* asrc = aP[p];
        const char* bsrc = bP[p];
        #pragma unroll
        for (int rep = 0; rep < 4; rep++) {
            int idx = tid + rep * 256;
            int row = idx >> 3;
            int q   = idx & 7;
            uint32_t dofs = (uint32_t)(row * SROW + q * 16);
            cp_async16(sAu + s * STAGE_BYTES + dofs,
                       asrc + (size_t)(m0 + row) * 1024 + kofs + q * 16);
            cp_async16(sBu + s * STAGE_BYTES + dofs,
                       bsrc + (size_t)(n0 + row) * 1024 + kofs + q * 16);
        }
        CP_COMMIT();
    };

    float acc[4][4][4];
    #pragma unroll
    for (int i = 0; i < 4; i++)
        #pragma unroll
        for (int j = 0; j < 4; j++)
            #pragma unroll
            for (int q = 0; q < 4; q++) acc[i][j][q] = 0.0f;

    const int lm  = lane & 15;
    const int lk8 = lane >> 4;
    const int bn  = (lane & 7) + ((lane >> 4) << 3);
    const int bk8 = (lane >> 3) & 1;

    const uint32_t aLaneOfs = (uint32_t)((wr * 64 + lm) * SROW + lk8 * 16);
    const uint32_t bLaneOfs = (uint32_t)((wc * 32 + bn) * SROW + bk8 * 16);

    load_iter(0);
    load_iter(1);

    for (int it = 0; it < NITER; it++) {
        int s = it % NSTAGE;
        if (it == NITER - 1) {
            asm volatile("cp.async.wait_group 0;" ::: "memory");
        } else {
            asm volatile("cp.async.wait_group 1;" ::: "memory");
        }
        __syncthreads();

        if (it + 2 < NITER) load_iter(it + 2);

        const uint32_t aStage = sAu + s * STAGE_BYTES + aLaneOfs;
        const uint32_t bStage = sBu + s * STAGE_BYTES + bLaneOfs;

        #pragma unroll
        for (int ks = 0; ks < 4; ks++) {
            uint32_t af[4][4];
            #pragma unroll
            for (int i = 0; i < 4; i++)
                ldsm_x4(af[i], aStage + i * (16 * SROW) + ks * 32);
            uint32_t bf[2][4];
            #pragma unroll
            for (int jp = 0; jp < 2; jp++)
                ldsm_x4(bf[jp], bStage + jp * (16 * SROW) + ks * 32);
            #pragma unroll
            for (int i = 0; i < 4; i++)
                #pragma unroll
                for (int j = 0; j < 4; j++)
                    mma16816(acc[i][j], af[i], &bf[j >> 1][(j & 1) * 2]);
        }
    }

    float* C = out + (size_t)b * NT * NX;
    #pragma unroll
    for (int i = 0; i < 4; i++) {
        int m_lo = m0 + wr * 64 + i * 16 + (lane >> 2);
        int m_hi = m_lo + 8;
        int or_lo = (m_lo - T0 + NT) & (NT - 1);
        int or_hi = (m_hi - T0 + NT) & (NT - 1);
        #pragma unroll
        for (int j = 0; j < 4; j++) {
            int col = n0 + wc * 32 + j * 8 + (lane & 3) * 2;
            *(float2*)(C + (size_t)or_lo * NX + col) = make_float2(acc[i][j][0], acc[i][j][1]);
            *(float2*)(C + (size_t)or_hi * NX + col) = make_float2(acc[i][j][2], acc[i][j][3]);
        }
    }
}

// ---------------------------------------------------------------------------
// Launch. Main stream: argmin(0), prepW(1), prep_phi(2), GEMM(3 <- profiled).
// Side stream (event fork/join): copy_Wf + single-kernel LU (2 nodes).
// ---------------------------------------------------------------------------
extern "C" void kernel_launch(void* const* d_in, const int* in_sizes, int n_in,
                              void* d_out, int out_size) {
    const float* phi = (const float*)d_in[0];
    const float* W   = (const float*)d_in[1];
    float* out = (float*)d_out;

    static cudaStream_t s_side = nullptr;
    static cudaEvent_t  s_fork = nullptr, s_join = nullptr;
    if (s_side == nullptr) {
        cudaStreamCreateWithFlags(&s_side, cudaStreamNonBlocking);
        cudaEventCreateWithFlags(&s_fork, cudaEventDisableTiming);
        cudaEventCreateWithFlags(&s_join, cudaEventDisableTiming);
        cudaFuncSetAttribute(gemm_tc_kernel,
                             cudaFuncAttributeMaxDynamicSharedMemorySize, G_SMEM);
        cudaFuncSetAttribute(lu_all,
                             cudaFuncAttributeMaxDynamicSharedMemorySize, LU_SMEM);
    }

    cudaEventRecord(s_fork, 0);
    cudaStreamWaitEvent(s_side, s_fork, 0);

    // ---- main stream ----
    argmin_kernel<<<NB, 32>>>(phi);                       // our launch 0
    {
        dim3 g(NX / 32, NX / 32), blk(32, 32);
        prep_W_bf16<<<g, blk>>>(W);                       // our launch 1
    }
    prep_phi_kernel<<<NB * NT, 128>>>(phi);               // our launch 2
    {
        dim3 grid(NX / BN, NT / BM, NB);
        gemm_tc_kernel<<<grid, 256, G_SMEM>>>(out);       // our launch 3 (ncu target)
    }

    // ---- side stream: fp32 logdet, 2 nodes ----
    copy_Wf<<<(NX * NX + 255) / 256, 256, 0, s_side>>>(W);
    lu_all<<<LUB, 512, LU_SMEM, s_side>>>(out + (out_size - NB));

    cudaEventRecord(s_join, s_side);
    cudaStreamWaitEvent(0, s_join, 0);
}